// round 1
// baseline (speedup 1.0000x reference)
#include <cuda_runtime.h>
#include <math.h>

// Problem constants
#define LL 2048
#define NB 2
#define EE 1024
#define HH 16
#define DD 64
#define FF 4096
#define ROWS (LL*NB)   // 4096

// ---------------- scratch (no allocation allowed) ----------------
__device__ float g_h  [ROWS*EE];
__device__ float g_q  [ROWS*EE];
__device__ float g_k  [ROWS*EE];
__device__ float g_v  [ROWS*EE];
__device__ float g_o  [ROWS*EE];
__device__ float g_x2 [ROWS*EE];
__device__ float g_h2 [ROWS*EE];
__device__ float g_mid[(size_t)ROWS*FF];

// ---------------- LayerNorm: one block per row, E=1024 ----------------
__global__ __launch_bounds__(256)
void ln_kernel(const float* __restrict__ x, const float* __restrict__ w,
               const float* __restrict__ b, float* __restrict__ out)
{
    int row = blockIdx.x;
    int tid = threadIdx.x;
    const float4* xr = (const float4*)(x + (size_t)row * EE);
    float4 v = xr[tid];                       // 256 threads * 4 = 1024
    float s  = v.x + v.y + v.z + v.w;
    float ss = v.x*v.x + v.y*v.y + v.z*v.z + v.w*v.w;
    #pragma unroll
    for (int o = 16; o > 0; o >>= 1) {
        s  += __shfl_xor_sync(0xffffffffu, s,  o);
        ss += __shfl_xor_sync(0xffffffffu, ss, o);
    }
    __shared__ float sbuf[8], ssbuf[8];
    if ((tid & 31) == 0) { sbuf[tid >> 5] = s; ssbuf[tid >> 5] = ss; }
    __syncthreads();
    float ts = 0.f, tss = 0.f;
    #pragma unroll
    for (int i = 0; i < 8; i++) { ts += sbuf[i]; tss += ssbuf[i]; }
    float mean = ts * (1.0f / EE);
    float var  = tss * (1.0f / EE) - mean * mean;
    float inv  = rsqrtf(var + 1e-5f);
    float4 w4 = ((const float4*)w)[tid];
    float4 b4 = ((const float4*)b)[tid];
    float4 o4;
    o4.x = (v.x - mean) * inv * w4.x + b4.x;
    o4.y = (v.y - mean) * inv * w4.y + b4.y;
    o4.z = (v.z - mean) * inv * w4.z + b4.z;
    o4.w = (v.w - mean) * inv * w4.w + b4.w;
    ((float4*)(out + (size_t)row * EE))[tid] = o4;
}

// ---------------- SGEMM (NT): C[m][n] = sum_k A[m][k]*B[n][k] + epi ----------------
// A: MxK row-major, B: NxK row-major (weight layout (out,in)), C: MxN row-major.
// 128x128 tile, BK=16, 256 threads, 8x8 per thread (split 4+4 blocking).
#define EPI_NONE  0
#define EPI_SCALE 1
#define EPI_RES   2
#define EPI_GELU  3

__device__ __forceinline__ float gelu_exact(float t) {
    return 0.5f * t * (1.0f + erff(t * 0.70710678118654752f));
}

template<int EPI>
__global__ __launch_bounds__(256, 2)
void gemm_nt(const float* __restrict__ A, const float* __restrict__ B,
             const float* __restrict__ bias, const float* __restrict__ res,
             float* __restrict__ C, int M, int Nn, int K, float scale)
{
    __shared__ float As[16][128];
    __shared__ float Bs[16][128];

    const int bm = blockIdx.y * 128;
    const int bn = blockIdx.x * 128;
    const int tid = threadIdx.x;
    const int tx = tid & 15;       // 16 col groups
    const int ty = tid >> 4;       // 16 row groups
    const int lrow = tid >> 1;     // 0..127 (tile row for loads)
    const int lk   = (tid & 1) * 8;// 0 or 8

    const float* Ap = A + (size_t)(bm + lrow) * K + lk;
    const float* Bp = B + (size_t)(bn + lrow) * K + lk;

    float acc[8][8];
    #pragma unroll
    for (int i = 0; i < 8; i++)
        #pragma unroll
        for (int j = 0; j < 8; j++) acc[i][j] = 0.f;

    // prefetch first tile into regs
    float4 a0 = *(const float4*)(Ap + 0);
    float4 a1 = *(const float4*)(Ap + 4);
    float4 b0 = *(const float4*)(Bp + 0);
    float4 b1 = *(const float4*)(Bp + 4);

    for (int k0 = 0; k0 < K; k0 += 16) {
        As[lk+0][lrow]=a0.x; As[lk+1][lrow]=a0.y; As[lk+2][lrow]=a0.z; As[lk+3][lrow]=a0.w;
        As[lk+4][lrow]=a1.x; As[lk+5][lrow]=a1.y; As[lk+6][lrow]=a1.z; As[lk+7][lrow]=a1.w;
        Bs[lk+0][lrow]=b0.x; Bs[lk+1][lrow]=b0.y; Bs[lk+2][lrow]=b0.z; Bs[lk+3][lrow]=b0.w;
        Bs[lk+4][lrow]=b1.x; Bs[lk+5][lrow]=b1.y; Bs[lk+6][lrow]=b1.z; Bs[lk+7][lrow]=b1.w;
        __syncthreads();

        // prefetch next tile (clamped so last iter re-loads current; values unused)
        int kn = (k0 + 16 < K) ? (k0 + 16) : k0;
        a0 = *(const float4*)(Ap + kn);
        a1 = *(const float4*)(Ap + kn + 4);
        b0 = *(const float4*)(Bp + kn);
        b1 = *(const float4*)(Bp + kn + 4);

        #pragma unroll
        for (int kk = 0; kk < 16; kk++) {
            float af[8], bf[8];
            *(float4*)&af[0] = *(const float4*)&As[kk][ty * 4];
            *(float4*)&af[4] = *(const float4*)&As[kk][64 + ty * 4];
            *(float4*)&bf[0] = *(const float4*)&Bs[kk][tx * 4];
            *(float4*)&bf[4] = *(const float4*)&Bs[kk][64 + tx * 4];
            #pragma unroll
            for (int i = 0; i < 8; i++)
                #pragma unroll
                for (int j = 0; j < 8; j++)
                    acc[i][j] += af[i] * bf[j];
        }
        __syncthreads();
    }

    // epilogue
    #pragma unroll
    for (int i = 0; i < 8; i++) {
        int row = bm + ((i < 4) ? (ty * 4 + i) : (64 + ty * 4 + i - 4));
        #pragma unroll
        for (int jh = 0; jh < 2; jh++) {
            int col = bn + ((jh == 0) ? (tx * 4) : (64 + tx * 4));
            float c[4];
            #pragma unroll
            for (int j = 0; j < 4; j++) c[j] = acc[i][jh * 4 + j] + bias[col + j];
            if (EPI == EPI_SCALE) {
                #pragma unroll
                for (int j = 0; j < 4; j++) c[j] *= scale;
            } else if (EPI == EPI_RES) {
                float4 r = *(const float4*)(res + (size_t)row * Nn + col);
                c[0] += r.x; c[1] += r.y; c[2] += r.z; c[3] += r.w;
            } else if (EPI == EPI_GELU) {
                #pragma unroll
                for (int j = 0; j < 4; j++) c[j] = gelu_exact(c[j]);
            }
            float4 o4 = make_float4(c[0], c[1], c[2], c[3]);
            *(float4*)(C + (size_t)row * Nn + col) = o4;
        }
    }
}

// ---------------- Flash attention, fp32, causal ----------------
// grid: (L/64, N*H); block: 256 threads. Smem: Qt[64d][64q], Kt[64d][64k],
// V[64k][64d], P[64q][64k] = 64KB dynamic.
__global__ __launch_bounds__(256)
void attn_kernel(const float* __restrict__ q, const float* __restrict__ k,
                 const float* __restrict__ v, float* __restrict__ o)
{
    extern __shared__ float sm[];
    float* Qs = sm;          // [d][row]   4096
    float* Ks = sm + 4096;   // [d][key]   4096
    float* Vs = sm + 8192;   // [key][d]   4096
    float* Ps = sm + 12288;  // [row][key] 4096

    const int qb = blockIdx.x;
    const int nh = blockIdx.y;
    const int n  = nh / HH;
    const int hh = nh % HH;
    const int tid = threadIdx.x;
    const int tx = tid & 15;
    const int ty = tid >> 4;

    // load Q tile transposed (d-major)
    #pragma unroll
    for (int t = 0; t < 4; t++) {
        int idx = tid + t * 256;          // float4 units, 0..1023
        int row = idx >> 4, c4 = idx & 15;
        int l = qb * 64 + row;
        float4 a = *(const float4*)(q + ((size_t)(l * NB + n) * EE + hh * DD + c4 * 4));
        Qs[(c4*4+0)*64 + row] = a.x;
        Qs[(c4*4+1)*64 + row] = a.y;
        Qs[(c4*4+2)*64 + row] = a.z;
        Qs[(c4*4+3)*64 + row] = a.w;
    }

    float m_i[4], l_i[4], accO[4][4];
    #pragma unroll
    for (int i = 0; i < 4; i++) {
        m_i[i] = -1e30f; l_i[i] = 0.f;
        #pragma unroll
        for (int j = 0; j < 4; j++) accO[i][j] = 0.f;
    }

    for (int jb = 0; jb <= qb; jb++) {
        __syncthreads();   // protect Ks/Vs/Ps from previous iteration readers
        #pragma unroll
        for (int t = 0; t < 4; t++) {
            int idx = tid + t * 256;
            int row = idx >> 4, c4 = idx & 15;
            int lkey = jb * 64 + row;
            size_t goff = (size_t)(lkey * NB + n) * EE + hh * DD + c4 * 4;
            float4 a = *(const float4*)(k + goff);
            Ks[(c4*4+0)*64 + row] = a.x;
            Ks[(c4*4+1)*64 + row] = a.y;
            Ks[(c4*4+2)*64 + row] = a.z;
            Ks[(c4*4+3)*64 + row] = a.w;
            float4 b = *(const float4*)(v + goff);
            *(float4*)&Vs[row * 64 + c4 * 4] = b;
        }
        __syncthreads();

        // S = Q K^T (64x64 tile, 4x4 per thread)
        float s[4][4];
        #pragma unroll
        for (int i = 0; i < 4; i++)
            #pragma unroll
            for (int j = 0; j < 4; j++) s[i][j] = 0.f;
        #pragma unroll
        for (int kk = 0; kk < 64; kk++) {
            float qf[4], kf[4];
            *(float4*)qf = *(const float4*)&Qs[kk * 64 + ty * 4];
            *(float4*)kf = *(const float4*)&Ks[kk * 64 + tx * 4];
            #pragma unroll
            for (int i = 0; i < 4; i++)
                #pragma unroll
                for (int j = 0; j < 4; j++)
                    s[i][j] += qf[i] * kf[j];
        }

        if (jb == qb) {   // causal mask within diagonal tile
            #pragma unroll
            for (int i = 0; i < 4; i++)
                #pragma unroll
                for (int j = 0; j < 4; j++)
                    if (tx * 4 + j > ty * 4 + i) s[i][j] = -1e30f;
        }

        // online softmax per row (row owned by 16 lanes sharing ty)
        #pragma unroll
        for (int i = 0; i < 4; i++) {
            float rmax = fmaxf(fmaxf(s[i][0], s[i][1]), fmaxf(s[i][2], s[i][3]));
            #pragma unroll
            for (int off = 1; off < 16; off <<= 1)
                rmax = fmaxf(rmax, __shfl_xor_sync(0xffffffffu, rmax, off));
            float mnew = fmaxf(m_i[i], rmax);
            float corr = __expf(m_i[i] - mnew);
            float p[4], rsum = 0.f;
            #pragma unroll
            for (int j = 0; j < 4; j++) { p[j] = __expf(s[i][j] - mnew); rsum += p[j]; }
            #pragma unroll
            for (int off = 1; off < 16; off <<= 1)
                rsum += __shfl_xor_sync(0xffffffffu, rsum, off);
            l_i[i] = l_i[i] * corr + rsum;
            m_i[i] = mnew;
            #pragma unroll
            for (int j = 0; j < 4; j++) accO[i][j] *= corr;
            *(float4*)&Ps[(ty * 4 + i) * 64 + tx * 4] = make_float4(p[0], p[1], p[2], p[3]);
        }
        __syncthreads();

        // O += P V
        #pragma unroll
        for (int kk = 0; kk < 64; kk++) {
            float vf[4];
            *(float4*)vf = *(const float4*)&Vs[kk * 64 + tx * 4];
            float pf[4];
            #pragma unroll
            for (int i = 0; i < 4; i++) pf[i] = Ps[(ty * 4 + i) * 64 + kk];
            #pragma unroll
            for (int i = 0; i < 4; i++)
                #pragma unroll
                for (int j = 0; j < 4; j++)
                    accO[i][j] += pf[i] * vf[j];
        }
    }

    // normalize + store
    #pragma unroll
    for (int i = 0; i < 4; i++) {
        float inv = 1.0f / l_i[i];
        int l = qb * 64 + ty * 4 + i;
        float4 r = make_float4(accO[i][0]*inv, accO[i][1]*inv, accO[i][2]*inv, accO[i][3]*inv);
        *(float4*)(o + ((size_t)(l * NB + n) * EE + hh * DD + tx * 4)) = r;
    }
}

// ---------------- launch ----------------
extern "C" void kernel_launch(void* const* d_in, const int* in_sizes, int n_in,
                              void* d_out, int out_size)
{
    const float* x     = (const float*)d_in[0];
    const float* ln1_w = (const float*)d_in[1];
    const float* ln1_b = (const float*)d_in[2];
    const float* wq    = (const float*)d_in[3];
    const float* bq    = (const float*)d_in[4];
    const float* wk    = (const float*)d_in[5];
    const float* bk    = (const float*)d_in[6];
    const float* wv    = (const float*)d_in[7];
    const float* bv    = (const float*)d_in[8];
    const float* wout  = (const float*)d_in[9];
    const float* bout  = (const float*)d_in[10];
    const float* ln2_w = (const float*)d_in[11];
    const float* ln2_b = (const float*)d_in[12];
    const float* fc1_w = (const float*)d_in[13];
    const float* fc1_b = (const float*)d_in[14];
    const float* fc2_w = (const float*)d_in[15];
    const float* fc2_b = (const float*)d_in[16];
    float* out = (float*)d_out;

    float *h, *q, *k, *v, *o, *x2, *h2, *mid;
    cudaGetSymbolAddress((void**)&h,   g_h);
    cudaGetSymbolAddress((void**)&q,   g_q);
    cudaGetSymbolAddress((void**)&k,   g_k);
    cudaGetSymbolAddress((void**)&v,   g_v);
    cudaGetSymbolAddress((void**)&o,   g_o);
    cudaGetSymbolAddress((void**)&x2,  g_x2);
    cudaGetSymbolAddress((void**)&h2,  g_h2);
    cudaGetSymbolAddress((void**)&mid, g_mid);

    cudaFuncSetAttribute(attn_kernel, cudaFuncAttributeMaxDynamicSharedMemorySize, 65536);

    const float scale = 0.125f;   // D^-0.5 = 1/8

    // LN1
    ln_kernel<<<ROWS, 256>>>(x, ln1_w, ln1_b, h);

    // QKV projections (M=4096, N=1024, K=1024)
    dim3 g1024(EE / 128, ROWS / 128);
    gemm_nt<EPI_SCALE><<<g1024, 256>>>(h, wq, bq, nullptr, q, ROWS, EE, EE, scale);
    gemm_nt<EPI_NONE ><<<g1024, 256>>>(h, wk, bk, nullptr, k, ROWS, EE, EE, 1.0f);
    gemm_nt<EPI_NONE ><<<g1024, 256>>>(h, wv, bv, nullptr, v, ROWS, EE, EE, 1.0f);

    // causal flash attention
    dim3 ga(LL / 64, NB * HH);
    attn_kernel<<<ga, 256, 65536>>>(q, k, v, o);

    // out projection + residual(x)
    gemm_nt<EPI_RES><<<g1024, 256>>>(o, wout, bout, x, x2, ROWS, EE, EE, 1.0f);

    // LN2
    ln_kernel<<<ROWS, 256>>>(x2, ln2_w, ln2_b, h2);

    // FC1 + GELU (M=4096, N=4096, K=1024)
    dim3 g4096(FF / 128, ROWS / 128);
    gemm_nt<EPI_GELU><<<g4096, 256>>>(h2, fc1_w, fc1_b, nullptr, mid, ROWS, FF, EE, 1.0f);

    // FC2 + residual(x2) -> out (M=4096, N=1024, K=4096)
    gemm_nt<EPI_RES><<<g1024, 256>>>(mid, fc2_w, fc2_b, x2, out, ROWS, EE, FF, 1.0f);
}

// round 2
// speedup vs baseline: 1.3379x; 1.3379x over previous
#include <cuda_runtime.h>
#include <math.h>
#include <stdint.h>

// Problem constants
#define LL 2048
#define NB 2
#define EE 1024
#define HH 16
#define DD 64
#define FF 4096
#define ROWS (LL*NB)   // 4096

// ---------------- scratch (no allocation allowed) ----------------
__device__ float g_h  [ROWS*EE];
__device__ float g_q  [ROWS*EE];
__device__ float g_k  [ROWS*EE];
__device__ float g_v  [ROWS*EE];
__device__ float g_o  [ROWS*EE];
__device__ float g_x2 [ROWS*EE];
__device__ float g_h2 [ROWS*EE];
__device__ float g_mid[(size_t)ROWS*FF];

// ---------------- LayerNorm: one block per row, E=1024 ----------------
__global__ __launch_bounds__(256)
void ln_kernel(const float* __restrict__ x, const float* __restrict__ w,
               const float* __restrict__ b, float* __restrict__ out)
{
    int row = blockIdx.x;
    int tid = threadIdx.x;
    const float4* xr = (const float4*)(x + (size_t)row * EE);
    float4 v = xr[tid];                       // 256 threads * 4 = 1024
    float s  = v.x + v.y + v.z + v.w;
    float ss = v.x*v.x + v.y*v.y + v.z*v.z + v.w*v.w;
    #pragma unroll
    for (int o = 16; o > 0; o >>= 1) {
        s  += __shfl_xor_sync(0xffffffffu, s,  o);
        ss += __shfl_xor_sync(0xffffffffu, ss, o);
    }
    __shared__ float sbuf[8], ssbuf[8];
    if ((tid & 31) == 0) { sbuf[tid >> 5] = s; ssbuf[tid >> 5] = ss; }
    __syncthreads();
    float ts = 0.f, tss = 0.f;
    #pragma unroll
    for (int i = 0; i < 8; i++) { ts += sbuf[i]; tss += ssbuf[i]; }
    float mean = ts * (1.0f / EE);
    float var  = tss * (1.0f / EE) - mean * mean;
    float inv  = rsqrtf(var + 1e-5f);
    float4 w4 = ((const float4*)w)[tid];
    float4 b4 = ((const float4*)b)[tid];
    float4 o4;
    o4.x = (v.x - mean) * inv * w4.x + b4.x;
    o4.y = (v.y - mean) * inv * w4.y + b4.y;
    o4.z = (v.z - mean) * inv * w4.z + b4.z;
    o4.w = (v.w - mean) * inv * w4.w + b4.w;
    ((float4*)(out + (size_t)row * EE))[tid] = o4;
}

// ---------------- TF32 tensor-core GEMM (NT) ----------------
// C[m][n] = sum_k A[m][k]*B[n][k] + epilogue.  A: MxK rm, B: NxK rm, C: MxN rm.
// 128x128 tile, BK=16, 256 thr (8 warps, 2x4 warp grid, 64x32 per warp),
// mma.sync.m16n8k8.tf32, fp32 accumulate.
#define EPI_NONE  0
#define EPI_SCALE 1
#define EPI_RES   2
#define EPI_GELU  3

__device__ __forceinline__ float gelu_exact(float t) {
    return 0.5f * t * (1.0f + erff(t * 0.70710678118654752f));
}

__device__ __forceinline__ uint32_t f2tf32(float f) {
    uint32_t r;
    asm("cvt.rna.tf32.f32 %0, %1;" : "=r"(r) : "f"(f));
    return r;
}

__device__ __forceinline__ void mma_tf32(float* c, const uint32_t* a, const uint32_t* b) {
    asm volatile(
        "mma.sync.aligned.m16n8k8.row.col.f32.tf32.tf32.f32 "
        "{%0,%1,%2,%3}, {%4,%5,%6,%7}, {%8,%9}, {%0,%1,%2,%3};\n"
        : "+f"(c[0]), "+f"(c[1]), "+f"(c[2]), "+f"(c[3])
        : "r"(a[0]), "r"(a[1]), "r"(a[2]), "r"(a[3]), "r"(b[0]), "r"(b[1]));
}

template<int EPI>
__global__ __launch_bounds__(256, 2)
void gemm_tc(const float* __restrict__ A, const float* __restrict__ B,
             const float* __restrict__ bias, const float* __restrict__ res,
             float* __restrict__ C, int M, int Nn, int K, float scale)
{
    __shared__ uint32_t As[16][132];   // [k][m], pad 4 -> conflict-free frag loads
    __shared__ uint32_t Bs[16][132];   // [k][n]

    const int bm = blockIdx.y * 128;
    const int bn = blockIdx.x * 128;
    const int tid  = threadIdx.x;
    const int warp = tid >> 5;
    const int lane = tid & 31;
    const int g = lane >> 2;           // group 0..7
    const int t = lane & 3;            // thread-in-group 0..3
    const int wm = (warp >> 2) * 64;   // warp m offset (0/64)
    const int wn = (warp & 3) * 32;    // warp n offset (0..96)

    const int lrow = tid >> 1;         // 0..127 (tile row for gmem loads)
    const int lcb  = (tid & 1) * 8;    // k-col base 0/8

    const float* Ap = A + (size_t)(bm + lrow) * K + lcb;
    const float* Bp = B + (size_t)(bn + lrow) * K + lcb;

    float c[4][4][4];                  // [mtile][ntile][creg]
    #pragma unroll
    for (int mt = 0; mt < 4; mt++)
        #pragma unroll
        for (int nt = 0; nt < 4; nt++)
            #pragma unroll
            for (int r = 0; r < 4; r++) c[mt][nt][r] = 0.f;

    // register prefetch of first tile
    float4 pa0 = *(const float4*)(Ap + 0);
    float4 pa1 = *(const float4*)(Ap + 4);
    float4 pb0 = *(const float4*)(Bp + 0);
    float4 pb1 = *(const float4*)(Bp + 4);

    for (int k0 = 0; k0 < K; k0 += 16) {
        As[lcb+0][lrow] = f2tf32(pa0.x); As[lcb+1][lrow] = f2tf32(pa0.y);
        As[lcb+2][lrow] = f2tf32(pa0.z); As[lcb+3][lrow] = f2tf32(pa0.w);
        As[lcb+4][lrow] = f2tf32(pa1.x); As[lcb+5][lrow] = f2tf32(pa1.y);
        As[lcb+6][lrow] = f2tf32(pa1.z); As[lcb+7][lrow] = f2tf32(pa1.w);
        Bs[lcb+0][lrow] = f2tf32(pb0.x); Bs[lcb+1][lrow] = f2tf32(pb0.y);
        Bs[lcb+2][lrow] = f2tf32(pb0.z); Bs[lcb+3][lrow] = f2tf32(pb0.w);
        Bs[lcb+4][lrow] = f2tf32(pb1.x); Bs[lcb+5][lrow] = f2tf32(pb1.y);
        Bs[lcb+6][lrow] = f2tf32(pb1.z); Bs[lcb+7][lrow] = f2tf32(pb1.w);
        __syncthreads();

        // prefetch next tile (clamped; last-iter values unused)
        int kn = (k0 + 16 < K) ? (k0 + 16) : k0;
        pa0 = *(const float4*)(Ap + kn);
        pa1 = *(const float4*)(Ap + kn + 4);
        pb0 = *(const float4*)(Bp + kn);
        pb1 = *(const float4*)(Bp + kn + 4);

        #pragma unroll
        for (int ks = 0; ks < 2; ks++) {
            const int kb = ks * 8;
            uint32_t af[4][4], bf[4][2];
            #pragma unroll
            for (int mt = 0; mt < 4; mt++) {
                int m = wm + mt * 16 + g;
                af[mt][0] = As[kb + t    ][m];
                af[mt][1] = As[kb + t    ][m + 8];
                af[mt][2] = As[kb + t + 4][m];
                af[mt][3] = As[kb + t + 4][m + 8];
            }
            #pragma unroll
            for (int nt = 0; nt < 4; nt++) {
                int n = wn + nt * 8 + g;
                bf[nt][0] = Bs[kb + t    ][n];
                bf[nt][1] = Bs[kb + t + 4][n];
            }
            #pragma unroll
            for (int mt = 0; mt < 4; mt++)
                #pragma unroll
                for (int nt = 0; nt < 4; nt++)
                    mma_tf32(c[mt][nt], af[mt], bf[nt]);
        }
        __syncthreads();
    }

    // epilogue: each thread owns 2-wide col chunks at (row g / g+8, col 2t,2t+1)
    #pragma unroll
    for (int mt = 0; mt < 4; mt++) {
        #pragma unroll
        for (int nt = 0; nt < 4; nt++) {
            int col = bn + wn + nt * 8 + t * 2;
            float2 bi = *(const float2*)(bias + col);
            #pragma unroll
            for (int h = 0; h < 2; h++) {
                int row = bm + wm + mt * 16 + g + h * 8;
                float v0 = c[mt][nt][h * 2 + 0] + bi.x;
                float v1 = c[mt][nt][h * 2 + 1] + bi.y;
                if (EPI == EPI_SCALE) { v0 *= scale; v1 *= scale; }
                else if (EPI == EPI_RES) {
                    float2 r = *(const float2*)(res + (size_t)row * Nn + col);
                    v0 += r.x; v1 += r.y;
                }
                else if (EPI == EPI_GELU) { v0 = gelu_exact(v0); v1 = gelu_exact(v1); }
                *(float2*)(C + (size_t)row * Nn + col) = make_float2(v0, v1);
            }
        }
    }
}

// ---------------- Flash attention, fp32, causal ----------------
__global__ __launch_bounds__(256)
void attn_kernel(const float* __restrict__ q, const float* __restrict__ k,
                 const float* __restrict__ v, float* __restrict__ o)
{
    extern __shared__ float sm[];
    float* Qs = sm;          // [d][row]   4096
    float* Ks = sm + 4096;   // [d][key]   4096
    float* Vs = sm + 8192;   // [key][d]   4096
    float* Ps = sm + 12288;  // [row][key] 4096

    const int qb = blockIdx.x;
    const int nh = blockIdx.y;
    const int n  = nh / HH;
    const int hh = nh % HH;
    const int tid = threadIdx.x;
    const int tx = tid & 15;
    const int ty = tid >> 4;

    #pragma unroll
    for (int t = 0; t < 4; t++) {
        int idx = tid + t * 256;
        int row = idx >> 4, c4 = idx & 15;
        int l = qb * 64 + row;
        float4 a = *(const float4*)(q + ((size_t)(l * NB + n) * EE + hh * DD + c4 * 4));
        Qs[(c4*4+0)*64 + row] = a.x;
        Qs[(c4*4+1)*64 + row] = a.y;
        Qs[(c4*4+2)*64 + row] = a.z;
        Qs[(c4*4+3)*64 + row] = a.w;
    }

    float m_i[4], l_i[4], accO[4][4];
    #pragma unroll
    for (int i = 0; i < 4; i++) {
        m_i[i] = -1e30f; l_i[i] = 0.f;
        #pragma unroll
        for (int j = 0; j < 4; j++) accO[i][j] = 0.f;
    }

    for (int jb = 0; jb <= qb; jb++) {
        __syncthreads();
        #pragma unroll
        for (int t = 0; t < 4; t++) {
            int idx = tid + t * 256;
            int row = idx >> 4, c4 = idx & 15;
            int lkey = jb * 64 + row;
            size_t goff = (size_t)(lkey * NB + n) * EE + hh * DD + c4 * 4;
            float4 a = *(const float4*)(k + goff);
            Ks[(c4*4+0)*64 + row] = a.x;
            Ks[(c4*4+1)*64 + row] = a.y;
            Ks[(c4*4+2)*64 + row] = a.z;
            Ks[(c4*4+3)*64 + row] = a.w;
            float4 b = *(const float4*)(v + goff);
            *(float4*)&Vs[row * 64 + c4 * 4] = b;
        }
        __syncthreads();

        float s[4][4];
        #pragma unroll
        for (int i = 0; i < 4; i++)
            #pragma unroll
            for (int j = 0; j < 4; j++) s[i][j] = 0.f;
        #pragma unroll
        for (int kk = 0; kk < 64; kk++) {
            float qf[4], kf[4];
            *(float4*)qf = *(const float4*)&Qs[kk * 64 + ty * 4];
            *(float4*)kf = *(const float4*)&Ks[kk * 64 + tx * 4];
            #pragma unroll
            for (int i = 0; i < 4; i++)
                #pragma unroll
                for (int j = 0; j < 4; j++)
                    s[i][j] += qf[i] * kf[j];
        }

        if (jb == qb) {
            #pragma unroll
            for (int i = 0; i < 4; i++)
                #pragma unroll
                for (int j = 0; j < 4; j++)
                    if (tx * 4 + j > ty * 4 + i) s[i][j] = -1e30f;
        }

        #pragma unroll
        for (int i = 0; i < 4; i++) {
            float rmax = fmaxf(fmaxf(s[i][0], s[i][1]), fmaxf(s[i][2], s[i][3]));
            #pragma unroll
            for (int off = 1; off < 16; off <<= 1)
                rmax = fmaxf(rmax, __shfl_xor_sync(0xffffffffu, rmax, off));
            float mnew = fmaxf(m_i[i], rmax);
            float corr = __expf(m_i[i] - mnew);
            float p[4], rsum = 0.f;
            #pragma unroll
            for (int j = 0; j < 4; j++) { p[j] = __expf(s[i][j] - mnew); rsum += p[j]; }
            #pragma unroll
            for (int off = 1; off < 16; off <<= 1)
                rsum += __shfl_xor_sync(0xffffffffu, rsum, off);
            l_i[i] = l_i[i] * corr + rsum;
            m_i[i] = mnew;
            #pragma unroll
            for (int j = 0; j < 4; j++) accO[i][j] *= corr;
            *(float4*)&Ps[(ty * 4 + i) * 64 + tx * 4] = make_float4(p[0], p[1], p[2], p[3]);
        }
        __syncthreads();

        #pragma unroll
        for (int kk = 0; kk < 64; kk++) {
            float vf[4];
            *(float4*)vf = *(const float4*)&Vs[kk * 64 + tx * 4];
            float pf[4];
            #pragma unroll
            for (int i = 0; i < 4; i++) pf[i] = Ps[(ty * 4 + i) * 64 + kk];
            #pragma unroll
            for (int i = 0; i < 4; i++)
                #pragma unroll
                for (int j = 0; j < 4; j++)
                    accO[i][j] += pf[i] * vf[j];
        }
    }

    #pragma unroll
    for (int i = 0; i < 4; i++) {
        float inv = 1.0f / l_i[i];
        int l = qb * 64 + ty * 4 + i;
        float4 r = make_float4(accO[i][0]*inv, accO[i][1]*inv, accO[i][2]*inv, accO[i][3]*inv);
        *(float4*)(o + ((size_t)(l * NB + n) * EE + hh * DD + tx * 4)) = r;
    }
}

// ---------------- launch ----------------
extern "C" void kernel_launch(void* const* d_in, const int* in_sizes, int n_in,
                              void* d_out, int out_size)
{
    const float* x     = (const float*)d_in[0];
    const float* ln1_w = (const float*)d_in[1];
    const float* ln1_b = (const float*)d_in[2];
    const float* wq    = (const float*)d_in[3];
    const float* bq    = (const float*)d_in[4];
    const float* wk    = (const float*)d_in[5];
    const float* bk    = (const float*)d_in[6];
    const float* wv    = (const float*)d_in[7];
    const float* bv    = (const float*)d_in[8];
    const float* wout  = (const float*)d_in[9];
    const float* bout  = (const float*)d_in[10];
    const float* ln2_w = (const float*)d_in[11];
    const float* ln2_b = (const float*)d_in[12];
    const float* fc1_w = (const float*)d_in[13];
    const float* fc1_b = (const float*)d_in[14];
    const float* fc2_w = (const float*)d_in[15];
    const float* fc2_b = (const float*)d_in[16];
    float* out = (float*)d_out;

    float *h, *q, *k, *v, *o, *x2, *h2, *mid;
    cudaGetSymbolAddress((void**)&h,   g_h);
    cudaGetSymbolAddress((void**)&q,   g_q);
    cudaGetSymbolAddress((void**)&k,   g_k);
    cudaGetSymbolAddress((void**)&v,   g_v);
    cudaGetSymbolAddress((void**)&o,   g_o);
    cudaGetSymbolAddress((void**)&x2,  g_x2);
    cudaGetSymbolAddress((void**)&h2,  g_h2);
    cudaGetSymbolAddress((void**)&mid, g_mid);

    cudaFuncSetAttribute(attn_kernel, cudaFuncAttributeMaxDynamicSharedMemorySize, 65536);

    const float scale = 0.125f;   // D^-0.5 = 1/8

    // LN1
    ln_kernel<<<ROWS, 256>>>(x, ln1_w, ln1_b, h);

    // QKV projections (M=4096, N=1024, K=1024)
    dim3 g1024(EE / 128, ROWS / 128);
    gemm_tc<EPI_SCALE><<<g1024, 256>>>(h, wq, bq, nullptr, q, ROWS, EE, EE, scale);
    gemm_tc<EPI_NONE ><<<g1024, 256>>>(h, wk, bk, nullptr, k, ROWS, EE, EE, 1.0f);
    gemm_tc<EPI_NONE ><<<g1024, 256>>>(h, wv, bv, nullptr, v, ROWS, EE, EE, 1.0f);

    // causal flash attention
    dim3 ga(LL / 64, NB * HH);
    attn_kernel<<<ga, 256, 65536>>>(q, k, v, o);

    // out projection + residual(x)
    gemm_tc<EPI_RES><<<g1024, 256>>>(o, wout, bout, x, x2, ROWS, EE, EE, 1.0f);

    // LN2
    ln_kernel<<<ROWS, 256>>>(x2, ln2_w, ln2_b, h2);

    // FC1 + GELU (M=4096, N=4096, K=1024)
    dim3 g4096(FF / 128, ROWS / 128);
    gemm_tc<EPI_GELU><<<g4096, 256>>>(h2, fc1_w, fc1_b, nullptr, mid, ROWS, FF, EE, 1.0f);

    // FC2 + residual(x2) -> out (M=4096, N=1024, K=4096)
    gemm_tc<EPI_RES><<<g1024, 256>>>(mid, fc2_w, fc2_b, x2, out, ROWS, EE, FF, 1.0f);
}

// round 3
// speedup vs baseline: 2.9412x; 2.1984x over previous
#include <cuda_runtime.h>
#include <math.h>
#include <stdint.h>

// Problem constants
#define LL 2048
#define NB 2
#define EE 1024
#define HH 16
#define DD 64
#define FF 4096
#define ROWS (LL*NB)   // 4096

// ---------------- scratch (no allocation allowed) ----------------
__device__ float g_h  [ROWS*EE];
__device__ float g_q  [ROWS*EE];
__device__ float g_k  [ROWS*EE];
__device__ float g_v  [ROWS*EE];
__device__ float g_o  [ROWS*EE];
__device__ float g_x2 [ROWS*EE];
__device__ float g_h2 [ROWS*EE];
__device__ float g_mid[(size_t)ROWS*FF];

// ---------------- small helpers ----------------
__device__ __forceinline__ uint32_t f2tf32(float f) {
    uint32_t r;
    asm("cvt.rna.tf32.f32 %0, %1;" : "=r"(r) : "f"(f));
    return r;
}
__device__ __forceinline__ uint32_t cvtb(uint32_t b) { return f2tf32(__uint_as_float(b)); }

__device__ __forceinline__ void mma_tf32(float* c, const uint32_t* a, const uint32_t* b) {
    asm volatile(
        "mma.sync.aligned.m16n8k8.row.col.f32.tf32.tf32.f32 "
        "{%0,%1,%2,%3}, {%4,%5,%6,%7}, {%8,%9}, {%0,%1,%2,%3};\n"
        : "+f"(c[0]), "+f"(c[1]), "+f"(c[2]), "+f"(c[3])
        : "r"(a[0]), "r"(a[1]), "r"(a[2]), "r"(a[3]), "r"(b[0]), "r"(b[1]));
}
__device__ __forceinline__ void ldsm4(uint32_t& r0, uint32_t& r1, uint32_t& r2, uint32_t& r3,
                                      uint32_t addr) {
    asm volatile("ldmatrix.sync.aligned.m8n8.x4.shared.b16 {%0,%1,%2,%3}, [%4];\n"
                 : "=r"(r0), "=r"(r1), "=r"(r2), "=r"(r3) : "r"(addr));
}
__device__ __forceinline__ void cp16(uint32_t saddr, const void* g) {
    asm volatile("cp.async.cg.shared.global [%0], [%1], 16;\n" :: "r"(saddr), "l"(g));
}
#define CP_COMMIT asm volatile("cp.async.commit_group;\n")
#define CP_WAIT1  asm volatile("cp.async.wait_group 1;\n")

__device__ __forceinline__ float gelu_exact(float t) {
    return 0.5f * t * (1.0f + erff(t * 0.70710678118654752f));
}

// ---------------- LayerNorm ----------------
__global__ __launch_bounds__(256)
void ln_kernel(const float* __restrict__ x, const float* __restrict__ w,
               const float* __restrict__ b, float* __restrict__ out)
{
    int row = blockIdx.x;
    int tid = threadIdx.x;
    const float4* xr = (const float4*)(x + (size_t)row * EE);
    float4 v = xr[tid];
    float s  = v.x + v.y + v.z + v.w;
    float ss = v.x*v.x + v.y*v.y + v.z*v.z + v.w*v.w;
    #pragma unroll
    for (int o = 16; o > 0; o >>= 1) {
        s  += __shfl_xor_sync(0xffffffffu, s,  o);
        ss += __shfl_xor_sync(0xffffffffu, ss, o);
    }
    __shared__ float sbuf[8], ssbuf[8];
    if ((tid & 31) == 0) { sbuf[tid >> 5] = s; ssbuf[tid >> 5] = ss; }
    __syncthreads();
    float ts = 0.f, tss = 0.f;
    #pragma unroll
    for (int i = 0; i < 8; i++) { ts += sbuf[i]; tss += ssbuf[i]; }
    float mean = ts * (1.0f / EE);
    float var  = tss * (1.0f / EE) - mean * mean;
    float inv  = rsqrtf(var + 1e-5f);
    float4 w4 = ((const float4*)w)[tid];
    float4 b4 = ((const float4*)b)[tid];
    float4 o4;
    o4.x = (v.x - mean) * inv * w4.x + b4.x;
    o4.y = (v.y - mean) * inv * w4.y + b4.y;
    o4.z = (v.z - mean) * inv * w4.z + b4.z;
    o4.w = (v.w - mean) * inv * w4.w + b4.w;
    ((float4*)(out + (size_t)row * EE))[tid] = o4;
}

// ---------------- pipelined TF32 GEMM core ----------------
// C[m][n] = sum_k A[m][k] * B[n][k].  BM=BN=128, BK=32, 2-stage cp.async.
// smem layout per stage: rows [m or n] x 32 k, row stride 36 floats (144B).
#define ASTRIDE 36
#define AS_ELE  (128*ASTRIDE)
#define GEMM_SMEM (4*AS_ELE*4)   // 2 stages x (A+B) x 4B = 73728

__device__ __forceinline__ void issue_tile(uint32_t smu, const float* A, const float* B,
                                           int bm, int bn, int K, int k0, int s)
{
    const int tid = threadIdx.x;
    uint32_t ao = smu + (unsigned)s * (AS_ELE*4);
    uint32_t bo = smu + (unsigned)(2+s) * (AS_ELE*4);
    #pragma unroll
    for (int c = 0; c < 4; c++) {
        int cid = tid + c * 256;
        int row = cid >> 3;
        int kc  = (cid & 7) * 4;
        cp16(ao + (row*ASTRIDE + kc)*4, A + (size_t)(bm+row)*K + k0 + kc);
        cp16(bo + (row*ASTRIDE + kc)*4, B + (size_t)(bn+row)*K + k0 + kc);
    }
}

__device__ __forceinline__ void gemm_main(const float* __restrict__ A,
                                          const float* __restrict__ B,
                                          int bm, int bn, int K, uint32_t smu,
                                          float c[4][4][4])
{
    const int tid  = threadIdx.x;
    const int warp = tid >> 5;
    const int lane = tid & 31;
    const int wm = (warp >> 2) * 64;
    const int wn = (warp & 3) * 32;
    const int arow = lane & 15;
    const int acol = (lane >> 4) * 4;
    const int brow = (lane & 7) + ((lane >> 4) << 3);
    const int bcol = ((lane >> 3) & 1) * 4;

    #pragma unroll
    for (int mt = 0; mt < 4; mt++)
        #pragma unroll
        for (int nt = 0; nt < 4; nt++)
            #pragma unroll
            for (int r = 0; r < 4; r++) c[mt][nt][r] = 0.f;

    const int NT = K >> 5;
    issue_tile(smu, A, B, bm, bn, K, 0, 0); CP_COMMIT;

    for (int kt = 0; kt < NT; kt++) {
        if (kt + 1 < NT) issue_tile(smu, A, B, bm, bn, K, (kt+1) << 5, (kt+1) & 1);
        CP_COMMIT;
        CP_WAIT1;
        __syncthreads();

        const int s = kt & 1;
        const uint32_t sa = smu + (unsigned)s * (AS_ELE*4);
        const uint32_t sb = smu + (unsigned)(2+s) * (AS_ELE*4);

        #pragma unroll
        for (int kb = 0; kb < 32; kb += 8) {
            uint32_t a[4][4];
            #pragma unroll
            for (int mt = 0; mt < 4; mt++) {
                ldsm4(a[mt][0], a[mt][1], a[mt][2], a[mt][3],
                      sa + (unsigned)(((wm + mt*16 + arow)*ASTRIDE) + kb + acol) * 4);
                a[mt][0] = cvtb(a[mt][0]); a[mt][1] = cvtb(a[mt][1]);
                a[mt][2] = cvtb(a[mt][2]); a[mt][3] = cvtb(a[mt][3]);
            }
            uint32_t bf[4][2];
            #pragma unroll
            for (int p = 0; p < 2; p++) {
                uint32_t r0, r1, r2, r3;
                ldsm4(r0, r1, r2, r3,
                      sb + (unsigned)(((wn + p*16 + brow)*ASTRIDE) + kb + bcol) * 4);
                bf[2*p][0]   = cvtb(r0); bf[2*p][1]   = cvtb(r1);
                bf[2*p+1][0] = cvtb(r2); bf[2*p+1][1] = cvtb(r3);
            }
            #pragma unroll
            for (int mt = 0; mt < 4; mt++)
                #pragma unroll
                for (int nt = 0; nt < 4; nt++)
                    mma_tf32(c[mt][nt], a[mt], bf[nt]);
        }
        __syncthreads();
    }
}

// ---------------- generic epilogue kernels ----------------
#define EPI_RES   2
#define EPI_GELU  3

template<int EPI>
__global__ __launch_bounds__(256, 2)
void gemm_tc(const float* __restrict__ A, const float* __restrict__ B,
             const float* __restrict__ bias, const float* __restrict__ res,
             float* __restrict__ C, int Nn, int K)
{
    extern __shared__ uint32_t smg[];
    uint32_t smu = (uint32_t)__cvta_generic_to_shared(smg);
    const int bm = blockIdx.y * 128;
    const int bn = blockIdx.x * 128;
    float c[4][4][4];
    gemm_main(A, B, bm, bn, K, smu, c);

    const int tid = threadIdx.x, warp = tid >> 5, lane = tid & 31;
    const int g = lane >> 2, t = lane & 3;
    const int wm = (warp >> 2) * 64, wn = (warp & 3) * 32;

    #pragma unroll
    for (int mt = 0; mt < 4; mt++) {
        #pragma unroll
        for (int nt = 0; nt < 4; nt++) {
            int col = bn + wn + nt * 8 + t * 2;
            float2 bi = *(const float2*)(bias + col);
            #pragma unroll
            for (int h = 0; h < 2; h++) {
                int row = bm + wm + mt * 16 + g + h * 8;
                float v0 = c[mt][nt][h*2+0] + bi.x;
                float v1 = c[mt][nt][h*2+1] + bi.y;
                if (EPI == EPI_RES) {
                    float2 r = *(const float2*)(res + (size_t)row * Nn + col);
                    v0 += r.x; v1 += r.y;
                } else if (EPI == EPI_GELU) {
                    v0 = gelu_exact(v0); v1 = gelu_exact(v1);
                }
                *(float2*)(C + (size_t)row * Nn + col) = make_float2(v0, v1);
            }
        }
    }
}

// ---------------- fused QKV projection ----------------
__global__ __launch_bounds__(256, 2)
void gemm_qkv(const float* __restrict__ A,
              const float* __restrict__ Bq, const float* __restrict__ Bk, const float* __restrict__ Bv,
              const float* __restrict__ bq, const float* __restrict__ bk, const float* __restrict__ bv,
              float* __restrict__ Cq, float* __restrict__ Ck, float* __restrict__ Cv, int K)
{
    extern __shared__ uint32_t smg[];
    uint32_t smu = (uint32_t)__cvta_generic_to_shared(smg);
    const int bm  = blockIdx.y * 128;
    const int bng = blockIdx.x * 128;
    const int seg = bng >> 10;
    const int bn  = bng & 1023;
    const float* B    = (seg == 0) ? Bq : (seg == 1) ? Bk : Bv;
    const float* bias = (seg == 0) ? bq : (seg == 1) ? bk : bv;
    float*       C    = (seg == 0) ? Cq : (seg == 1) ? Ck : Cv;
    const float scale = (seg == 0) ? 0.125f : 1.0f;   // D^-0.5 fused into Q

    float c[4][4][4];
    gemm_main(A, B, bm, bn, K, smu, c);

    const int tid = threadIdx.x, warp = tid >> 5, lane = tid & 31;
    const int g = lane >> 2, t = lane & 3;
    const int wm = (warp >> 2) * 64, wn = (warp & 3) * 32;

    #pragma unroll
    for (int mt = 0; mt < 4; mt++) {
        #pragma unroll
        for (int nt = 0; nt < 4; nt++) {
            int col = bn + wn + nt * 8 + t * 2;
            float2 bi = *(const float2*)(bias + col);
            #pragma unroll
            for (int h = 0; h < 2; h++) {
                int row = bm + wm + mt * 16 + g + h * 8;
                float v0 = (c[mt][nt][h*2+0] + bi.x) * scale;
                float v1 = (c[mt][nt][h*2+1] + bi.y) * scale;
                *(float2*)(C + (size_t)row * 1024 + col) = make_float2(v0, v1);
            }
        }
    }
}

// ---------------- flash attention with tf32 tensor cores ----------------
// Br=Bc=64, 128 threads (4 warps); each warp: 16 q-rows x full 64-key tile.
// smem (tf32 bits): Qs[64][68], Ks[64][68], Vt[64][68] (V transposed, d-major).
#define ATT_STRIDE 68
#define ATT_SMEM  (3*64*ATT_STRIDE*4)   // 52224 B

__global__ __launch_bounds__(128)
void attn_tc(const float* __restrict__ q, const float* __restrict__ k,
             const float* __restrict__ v, float* __restrict__ o)
{
    extern __shared__ uint32_t smA[];
    uint32_t* Qs = smA;
    uint32_t* Ks = smA + 64*ATT_STRIDE;
    uint32_t* Vt = smA + 2*64*ATT_STRIDE;
    const uint32_t qsu = (uint32_t)__cvta_generic_to_shared(Qs);
    const uint32_t ksu = (uint32_t)__cvta_generic_to_shared(Ks);
    const uint32_t vsu = (uint32_t)__cvta_generic_to_shared(Vt);

    const int qb = blockIdx.x;
    const int nh = blockIdx.y;
    const int n  = nh / HH;
    const int hh = nh % HH;
    const int tid  = threadIdx.x;
    const int warp = tid >> 5;
    const int lane = tid & 31;
    const int g = lane >> 2, t = lane & 3;
    const int m0 = warp * 16;
    const int arow = lane & 15, acol = (lane >> 4) * 4;
    const int brow = (lane & 7) + ((lane >> 4) << 3), bcol = ((lane >> 3) & 1) * 4;

    // load Q tile (pre-scaled in projection), convert to tf32
    #pragma unroll
    for (int f = 0; f < 8; f++) {
        int fid = tid + f * 128;
        int row = fid >> 4, c4 = fid & 15;
        float4 a = *(const float4*)(q + ((size_t)((qb*64+row)*NB + n)*EE + hh*DD + c4*4));
        uint4 u;
        u.x = f2tf32(a.x); u.y = f2tf32(a.y); u.z = f2tf32(a.z); u.w = f2tf32(a.w);
        *(uint4*)&Qs[row*ATT_STRIDE + c4*4] = u;
    }

    float m_i[2] = {-1e30f, -1e30f};
    float l_i[2] = {0.f, 0.f};
    float accO[8][4];
    #pragma unroll
    for (int dt = 0; dt < 8; dt++)
        #pragma unroll
        for (int r = 0; r < 4; r++) accO[dt][r] = 0.f;

    for (int jb = 0; jb <= qb; jb++) {
        __syncthreads();
        // load K, V tiles (convert to tf32; V transposed -> Vt[d][key])
        #pragma unroll
        for (int f = 0; f < 8; f++) {
            int fid = tid + f * 128;
            int row = fid >> 4, c4 = fid & 15;
            size_t goff = (size_t)((jb*64+row)*NB + n)*EE + hh*DD + c4*4;
            float4 a = *(const float4*)(k + goff);
            uint4 u;
            u.x = f2tf32(a.x); u.y = f2tf32(a.y); u.z = f2tf32(a.z); u.w = f2tf32(a.w);
            *(uint4*)&Ks[row*ATT_STRIDE + c4*4] = u;
            float4 b = *(const float4*)(v + goff);
            Vt[(c4*4+0)*ATT_STRIDE + row] = f2tf32(b.x);
            Vt[(c4*4+1)*ATT_STRIDE + row] = f2tf32(b.y);
            Vt[(c4*4+2)*ATT_STRIDE + row] = f2tf32(b.z);
            Vt[(c4*4+3)*ATT_STRIDE + row] = f2tf32(b.w);
        }
        __syncthreads();

        // S = Q K^T  (16 x 64 per warp)
        float sc[8][4];
        #pragma unroll
        for (int nt = 0; nt < 8; nt++)
            #pragma unroll
            for (int r = 0; r < 4; r++) sc[nt][r] = 0.f;

        #pragma unroll
        for (int kc = 0; kc < 8; kc++) {
            uint32_t a[4];
            ldsm4(a[0], a[1], a[2], a[3],
                  qsu + (unsigned)((m0 + arow)*ATT_STRIDE + kc*8 + acol) * 4);
            #pragma unroll
            for (int p = 0; p < 4; p++) {
                uint32_t r0, r1, r2, r3;
                ldsm4(r0, r1, r2, r3,
                      ksu + (unsigned)((p*16 + brow)*ATT_STRIDE + kc*8 + bcol) * 4);
                uint32_t b0[2] = {r0, r1}, b1[2] = {r2, r3};
                mma_tf32(sc[2*p],   a, b0);
                mma_tf32(sc[2*p+1], a, b1);
            }
        }

        // causal mask on diagonal tile (local indices)
        if (jb == qb) {
            int r0 = m0 + g, r1 = m0 + g + 8;
            #pragma unroll
            for (int nt = 0; nt < 8; nt++) {
                int col = nt * 8 + t * 2;
                if (col     > r0) sc[nt][0] = -1e30f;
                if (col + 1 > r0) sc[nt][1] = -1e30f;
                if (col     > r1) sc[nt][2] = -1e30f;
                if (col + 1 > r1) sc[nt][3] = -1e30f;
            }
        }

        // online softmax (rows g and g+8; row scope = quad of 4 lanes)
        float mx0 = -1e30f, mx1 = -1e30f;
        #pragma unroll
        for (int nt = 0; nt < 8; nt++) {
            mx0 = fmaxf(mx0, fmaxf(sc[nt][0], sc[nt][1]));
            mx1 = fmaxf(mx1, fmaxf(sc[nt][2], sc[nt][3]));
        }
        #pragma unroll
        for (int off = 1; off < 4; off <<= 1) {
            mx0 = fmaxf(mx0, __shfl_xor_sync(0xffffffffu, mx0, off));
            mx1 = fmaxf(mx1, __shfl_xor_sync(0xffffffffu, mx1, off));
        }
        float mn0 = fmaxf(m_i[0], mx0), mn1 = fmaxf(m_i[1], mx1);
        float corr0 = __expf(m_i[0] - mn0), corr1 = __expf(m_i[1] - mn1);
        float sum0 = 0.f, sum1 = 0.f;
        #pragma unroll
        for (int nt = 0; nt < 8; nt++) {
            sc[nt][0] = __expf(sc[nt][0] - mn0); sum0 += sc[nt][0];
            sc[nt][1] = __expf(sc[nt][1] - mn0); sum0 += sc[nt][1];
            sc[nt][2] = __expf(sc[nt][2] - mn1); sum1 += sc[nt][2];
            sc[nt][3] = __expf(sc[nt][3] - mn1); sum1 += sc[nt][3];
        }
        #pragma unroll
        for (int off = 1; off < 4; off <<= 1) {
            sum0 += __shfl_xor_sync(0xffffffffu, sum0, off);
            sum1 += __shfl_xor_sync(0xffffffffu, sum1, off);
        }
        l_i[0] = l_i[0] * corr0 + sum0;
        l_i[1] = l_i[1] * corr1 + sum1;
        m_i[0] = mn0; m_i[1] = mn1;
        #pragma unroll
        for (int dt = 0; dt < 8; dt++) {
            accO[dt][0] *= corr0; accO[dt][1] *= corr0;
            accO[dt][2] *= corr1; accO[dt][3] *= corr1;
        }

        // O += P V  (P fragments built from sc via quad shuffles)
        #pragma unroll
        for (int kc = 0; kc < 8; kc++) {
            const int bl   = lane & 28;
            const int src0 = bl | (t >> 1);
            const int src1 = src0 + 2;
            float u0 = __shfl_sync(0xffffffffu, sc[kc][0], src0);
            float u1 = __shfl_sync(0xffffffffu, sc[kc][1], src0);
            float w0 = __shfl_sync(0xffffffffu, sc[kc][0], src1);
            float w1 = __shfl_sync(0xffffffffu, sc[kc][1], src1);
            float x0 = __shfl_sync(0xffffffffu, sc[kc][2], src0);
            float x1 = __shfl_sync(0xffffffffu, sc[kc][3], src0);
            float y0 = __shfl_sync(0xffffffffu, sc[kc][2], src1);
            float y1 = __shfl_sync(0xffffffffu, sc[kc][3], src1);
            uint32_t a[4];
            a[0] = f2tf32((t & 1) ? u1 : u0);   // P[g   ][kc*8 + t    ]
            a[1] = f2tf32((t & 1) ? x1 : x0);   // P[g+8 ][kc*8 + t    ]
            a[2] = f2tf32((t & 1) ? w1 : w0);   // P[g   ][kc*8 + t + 4]
            a[3] = f2tf32((t & 1) ? y1 : y0);   // P[g+8 ][kc*8 + t + 4]
            #pragma unroll
            for (int p = 0; p < 4; p++) {
                uint32_t r0, r1, r2, r3;
                ldsm4(r0, r1, r2, r3,
                      vsu + (unsigned)((p*16 + brow)*ATT_STRIDE + kc*8 + bcol) * 4);
                uint32_t b0[2] = {r0, r1}, b1[2] = {r2, r3};
                mma_tf32(accO[2*p],   a, b0);
                mma_tf32(accO[2*p+1], a, b1);
            }
        }
    }

    // normalize + store
    float inv0 = 1.0f / l_i[0], inv1 = 1.0f / l_i[1];
    int l0 = qb*64 + m0 + g;
    int l1 = l0 + 8;
    #pragma unroll
    for (int dt = 0; dt < 8; dt++) {
        int d = hh*DD + dt*8 + t*2;
        *(float2*)(o + ((size_t)(l0*NB + n)*EE + d)) =
            make_float2(accO[dt][0]*inv0, accO[dt][1]*inv0);
        *(float2*)(o + ((size_t)(l1*NB + n)*EE + d)) =
            make_float2(accO[dt][2]*inv1, accO[dt][3]*inv1);
    }
}

// ---------------- launch ----------------
extern "C" void kernel_launch(void* const* d_in, const int* in_sizes, int n_in,
                              void* d_out, int out_size)
{
    const float* x     = (const float*)d_in[0];
    const float* ln1_w = (const float*)d_in[1];
    const float* ln1_b = (const float*)d_in[2];
    const float* wq    = (const float*)d_in[3];
    const float* bq    = (const float*)d_in[4];
    const float* wk    = (const float*)d_in[5];
    const float* bk    = (const float*)d_in[6];
    const float* wv    = (const float*)d_in[7];
    const float* bv    = (const float*)d_in[8];
    const float* wout  = (const float*)d_in[9];
    const float* bout  = (const float*)d_in[10];
    const float* ln2_w = (const float*)d_in[11];
    const float* ln2_b = (const float*)d_in[12];
    const float* fc1_w = (const float*)d_in[13];
    const float* fc1_b = (const float*)d_in[14];
    const float* fc2_w = (const float*)d_in[15];
    const float* fc2_b = (const float*)d_in[16];
    float* out = (float*)d_out;

    float *h, *q, *k, *v, *o, *x2, *h2, *mid;
    cudaGetSymbolAddress((void**)&h,   g_h);
    cudaGetSymbolAddress((void**)&q,   g_q);
    cudaGetSymbolAddress((void**)&k,   g_k);
    cudaGetSymbolAddress((void**)&v,   g_v);
    cudaGetSymbolAddress((void**)&o,   g_o);
    cudaGetSymbolAddress((void**)&x2,  g_x2);
    cudaGetSymbolAddress((void**)&h2,  g_h2);
    cudaGetSymbolAddress((void**)&mid, g_mid);

    cudaFuncSetAttribute(gemm_qkv,         cudaFuncAttributeMaxDynamicSharedMemorySize, GEMM_SMEM);
    cudaFuncSetAttribute(gemm_tc<EPI_RES>, cudaFuncAttributeMaxDynamicSharedMemorySize, GEMM_SMEM);
    cudaFuncSetAttribute(gemm_tc<EPI_GELU>,cudaFuncAttributeMaxDynamicSharedMemorySize, GEMM_SMEM);
    cudaFuncSetAttribute(attn_tc,          cudaFuncAttributeMaxDynamicSharedMemorySize, ATT_SMEM);

    // LN1
    ln_kernel<<<ROWS, 256>>>(x, ln1_w, ln1_b, h);

    // fused QKV projection (M=4096, N=3*1024, K=1024); scale fused into Q
    dim3 gqkv(3 * EE / 128, ROWS / 128);
    gemm_qkv<<<gqkv, 256, GEMM_SMEM>>>(h, wq, wk, wv, bq, bk, bv, q, k, v, EE);

    // causal flash attention (tf32 tensor cores)
    dim3 ga(LL / 64, NB * HH);
    attn_tc<<<ga, 128, ATT_SMEM>>>(q, k, v, o);

    // out projection + residual(x)
    dim3 g1024(EE / 128, ROWS / 128);
    gemm_tc<EPI_RES><<<g1024, 256, GEMM_SMEM>>>(o, wout, bout, x, x2, EE, EE);

    // LN2
    ln_kernel<<<ROWS, 256>>>(x2, ln2_w, ln2_b, h2);

    // FC1 + GELU (M=4096, N=4096, K=1024)
    dim3 g4096(FF / 128, ROWS / 128);
    gemm_tc<EPI_GELU><<<g4096, 256, GEMM_SMEM>>>(h2, fc1_w, fc1_b, nullptr, mid, FF, EE);

    // FC2 + residual(x2) -> out (M=4096, N=1024, K=4096)
    gemm_tc<EPI_RES><<<g1024, 256, GEMM_SMEM>>>(mid, fc2_w, fc2_b, x2, out, EE, FF);
}

// round 4
// speedup vs baseline: 3.1375x; 1.0667x over previous
#include <cuda_runtime.h>
#include <math.h>
#include <stdint.h>

// Problem constants
#define LL 2048
#define NB 2
#define EE 1024
#define HH 16
#define DD 64
#define FF 4096
#define ROWS (LL*NB)   // 4096

// ---------------- scratch (no allocation allowed) ----------------
__device__ float g_h  [ROWS*EE];
__device__ float g_q  [ROWS*EE];
__device__ float g_k  [ROWS*EE];
__device__ float g_v  [ROWS*EE];
__device__ float g_o  [ROWS*EE];
__device__ float g_x2 [ROWS*EE];
__device__ float g_h2 [ROWS*EE];
__device__ float g_mid[(size_t)ROWS*FF];

// ---------------- small helpers ----------------
// NOTE: mma.tf32 uses only the upper 19 bits of the b32 operand; raw fp32 bit
// patterns are valid tf32 operands (truncation rounding, CUTLASS-style).
__device__ __forceinline__ void mma_tf32(float* c, const uint32_t* a, const uint32_t* b) {
    asm volatile(
        "mma.sync.aligned.m16n8k8.row.col.f32.tf32.tf32.f32 "
        "{%0,%1,%2,%3}, {%4,%5,%6,%7}, {%8,%9}, {%0,%1,%2,%3};\n"
        : "+f"(c[0]), "+f"(c[1]), "+f"(c[2]), "+f"(c[3])
        : "r"(a[0]), "r"(a[1]), "r"(a[2]), "r"(a[3]), "r"(b[0]), "r"(b[1]));
}
__device__ __forceinline__ void ldsm4(uint32_t& r0, uint32_t& r1, uint32_t& r2, uint32_t& r3,
                                      uint32_t addr) {
    asm volatile("ldmatrix.sync.aligned.m8n8.x4.shared.b16 {%0,%1,%2,%3}, [%4];\n"
                 : "=r"(r0), "=r"(r1), "=r"(r2), "=r"(r3) : "r"(addr));
}
__device__ __forceinline__ void cp16(uint32_t saddr, const void* g) {
    asm volatile("cp.async.cg.shared.global [%0], [%1], 16;\n" :: "r"(saddr), "l"(g));
}
#define CP_COMMIT asm volatile("cp.async.commit_group;\n")
#define CP_WAIT1  asm volatile("cp.async.wait_group 1;\n")

__device__ __forceinline__ float gelu_exact(float t) {
    return 0.5f * t * (1.0f + erff(t * 0.70710678118654752f));
}

// ---------------- LayerNorm ----------------
__global__ __launch_bounds__(256)
void ln_kernel(const float* __restrict__ x, const float* __restrict__ w,
               const float* __restrict__ b, float* __restrict__ out)
{
    int row = blockIdx.x;
    int tid = threadIdx.x;
    const float4* xr = (const float4*)(x + (size_t)row * EE);
    float4 v = xr[tid];
    float s  = v.x + v.y + v.z + v.w;
    float ss = v.x*v.x + v.y*v.y + v.z*v.z + v.w*v.w;
    #pragma unroll
    for (int o = 16; o > 0; o >>= 1) {
        s  += __shfl_xor_sync(0xffffffffu, s,  o);
        ss += __shfl_xor_sync(0xffffffffu, ss, o);
    }
    __shared__ float sbuf[8], ssbuf[8];
    if ((tid & 31) == 0) { sbuf[tid >> 5] = s; ssbuf[tid >> 5] = ss; }
    __syncthreads();
    float ts = 0.f, tss = 0.f;
    #pragma unroll
    for (int i = 0; i < 8; i++) { ts += sbuf[i]; tss += ssbuf[i]; }
    float mean = ts * (1.0f / EE);
    float var  = tss * (1.0f / EE) - mean * mean;
    float inv  = rsqrtf(var + 1e-5f);
    float4 w4 = ((const float4*)w)[tid];
    float4 b4 = ((const float4*)b)[tid];
    float4 o4;
    o4.x = (v.x - mean) * inv * w4.x + b4.x;
    o4.y = (v.y - mean) * inv * w4.y + b4.y;
    o4.z = (v.z - mean) * inv * w4.z + b4.z;
    o4.w = (v.w - mean) * inv * w4.w + b4.w;
    ((float4*)(out + (size_t)row * EE))[tid] = o4;
}

// ---------------- pipelined TF32 GEMM core ----------------
// C[m][n] = sum_k A[m][k] * B[n][k].  BM=BN=128, BK=32, 2-stage cp.async.
#define ASTRIDE 36
#define AS_ELE  (128*ASTRIDE)
#define GEMM_SMEM (4*AS_ELE*4)   // 73728 B

__device__ __forceinline__ void issue_tile(uint32_t smu, const float* A, const float* B,
                                           int bm, int bn, int K, int k0, int s)
{
    const int tid = threadIdx.x;
    uint32_t ao = smu + (unsigned)s * (AS_ELE*4);
    uint32_t bo = smu + (unsigned)(2+s) * (AS_ELE*4);
    #pragma unroll
    for (int c = 0; c < 4; c++) {
        int cid = tid + c * 256;
        int row = cid >> 3;
        int kc  = (cid & 7) * 4;
        cp16(ao + (row*ASTRIDE + kc)*4, A + (size_t)(bm+row)*K + k0 + kc);
        cp16(bo + (row*ASTRIDE + kc)*4, B + (size_t)(bn+row)*K + k0 + kc);
    }
}

__device__ __forceinline__ void gemm_main(const float* __restrict__ A,
                                          const float* __restrict__ B,
                                          int bm, int bn, int K, uint32_t smu,
                                          float c[4][4][4])
{
    const int tid  = threadIdx.x;
    const int warp = tid >> 5;
    const int lane = tid & 31;
    const int wm = (warp >> 2) * 64;
    const int wn = (warp & 3) * 32;
    const int arow = lane & 15;
    const int acol = (lane >> 4) * 4;
    const int brow = (lane & 7) + ((lane >> 4) << 3);
    const int bcol = ((lane >> 3) & 1) * 4;

    #pragma unroll
    for (int mt = 0; mt < 4; mt++)
        #pragma unroll
        for (int nt = 0; nt < 4; nt++)
            #pragma unroll
            for (int r = 0; r < 4; r++) c[mt][nt][r] = 0.f;

    const int NT = K >> 5;
    issue_tile(smu, A, B, bm, bn, K, 0, 0); CP_COMMIT;

    for (int kt = 0; kt < NT; kt++) {
        if (kt + 1 < NT) issue_tile(smu, A, B, bm, bn, K, (kt+1) << 5, (kt+1) & 1);
        CP_COMMIT;
        CP_WAIT1;
        __syncthreads();

        const int s = kt & 1;
        const uint32_t sa = smu + (unsigned)s * (AS_ELE*4);
        const uint32_t sb = smu + (unsigned)(2+s) * (AS_ELE*4);

        #pragma unroll
        for (int kb = 0; kb < 32; kb += 8) {
            uint32_t a[4][4];
            #pragma unroll
            for (int mt = 0; mt < 4; mt++)
                ldsm4(a[mt][0], a[mt][1], a[mt][2], a[mt][3],
                      sa + (unsigned)(((wm + mt*16 + arow)*ASTRIDE) + kb + acol) * 4);
            uint32_t bf[4][2];
            #pragma unroll
            for (int p = 0; p < 2; p++) {
                uint32_t r0, r1, r2, r3;
                ldsm4(r0, r1, r2, r3,
                      sb + (unsigned)(((wn + p*16 + brow)*ASTRIDE) + kb + bcol) * 4);
                bf[2*p][0]   = r0; bf[2*p][1]   = r1;
                bf[2*p+1][0] = r2; bf[2*p+1][1] = r3;
            }
            #pragma unroll
            for (int mt = 0; mt < 4; mt++)
                #pragma unroll
                for (int nt = 0; nt < 4; nt++)
                    mma_tf32(c[mt][nt], a[mt], bf[nt]);
        }
        __syncthreads();
    }
}

// ---------------- generic epilogue kernels ----------------
#define EPI_RES   2
#define EPI_GELU  3

template<int EPI>
__global__ __launch_bounds__(256, 2)
void gemm_tc(const float* __restrict__ A, const float* __restrict__ B,
             const float* __restrict__ bias, const float* __restrict__ res,
             float* __restrict__ C, int Nn, int K)
{
    extern __shared__ uint32_t smg[];
    uint32_t smu = (uint32_t)__cvta_generic_to_shared(smg);
    const int bm = blockIdx.y * 128;
    const int bn = blockIdx.x * 128;
    float c[4][4][4];
    gemm_main(A, B, bm, bn, K, smu, c);

    const int tid = threadIdx.x, warp = tid >> 5, lane = tid & 31;
    const int g = lane >> 2, t = lane & 3;
    const int wm = (warp >> 2) * 64, wn = (warp & 3) * 32;

    #pragma unroll
    for (int mt = 0; mt < 4; mt++) {
        #pragma unroll
        for (int nt = 0; nt < 4; nt++) {
            int col = bn + wn + nt * 8 + t * 2;
            float2 bi = *(const float2*)(bias + col);
            #pragma unroll
            for (int h = 0; h < 2; h++) {
                int row = bm + wm + mt * 16 + g + h * 8;
                float v0 = c[mt][nt][h*2+0] + bi.x;
                float v1 = c[mt][nt][h*2+1] + bi.y;
                if (EPI == EPI_RES) {
                    float2 r = *(const float2*)(res + (size_t)row * Nn + col);
                    v0 += r.x; v1 += r.y;
                } else if (EPI == EPI_GELU) {
                    v0 = gelu_exact(v0); v1 = gelu_exact(v1);
                }
                *(float2*)(C + (size_t)row * Nn + col) = make_float2(v0, v1);
            }
        }
    }
}

// ---------------- fused QKV projection ----------------
__global__ __launch_bounds__(256, 2)
void gemm_qkv(const float* __restrict__ A,
              const float* __restrict__ Bq, const float* __restrict__ Bk, const float* __restrict__ Bv,
              const float* __restrict__ bq, const float* __restrict__ bk, const float* __restrict__ bv,
              float* __restrict__ Cq, float* __restrict__ Ck, float* __restrict__ Cv, int K)
{
    extern __shared__ uint32_t smg[];
    uint32_t smu = (uint32_t)__cvta_generic_to_shared(smg);
    const int bm  = blockIdx.y * 128;
    const int bng = blockIdx.x * 128;
    const int seg = bng >> 10;
    const int bn  = bng & 1023;
    const float* B    = (seg == 0) ? Bq : (seg == 1) ? Bk : Bv;
    const float* bias = (seg == 0) ? bq : (seg == 1) ? bk : bv;
    float*       C    = (seg == 0) ? Cq : (seg == 1) ? Ck : Cv;
    const float scale = (seg == 0) ? 0.125f : 1.0f;   // D^-0.5 fused into Q

    float c[4][4][4];
    gemm_main(A, B, bm, bn, K, smu, c);

    const int tid = threadIdx.x, warp = tid >> 5, lane = tid & 31;
    const int g = lane >> 2, t = lane & 3;
    const int wm = (warp >> 2) * 64, wn = (warp & 3) * 32;

    #pragma unroll
    for (int mt = 0; mt < 4; mt++) {
        #pragma unroll
        for (int nt = 0; nt < 4; nt++) {
            int col = bn + wn + nt * 8 + t * 2;
            float2 bi = *(const float2*)(bias + col);
            #pragma unroll
            for (int h = 0; h < 2; h++) {
                int row = bm + wm + mt * 16 + g + h * 8;
                float v0 = (c[mt][nt][h*2+0] + bi.x) * scale;
                float v1 = (c[mt][nt][h*2+1] + bi.y) * scale;
                *(float2*)(C + (size_t)row * 1024 + col) = make_float2(v0, v1);
            }
        }
    }
}

// ---------------- flash attention with tf32 tensor cores ----------------
#define ATT_STRIDE 68
#define ATT_SMEM  (3*64*ATT_STRIDE*4)   // 52224 B

__global__ __launch_bounds__(128)
void attn_tc(const float* __restrict__ q, const float* __restrict__ k,
             const float* __restrict__ v, float* __restrict__ o)
{
    extern __shared__ uint32_t smA[];
    uint32_t* Qs = smA;
    uint32_t* Ks = smA + 64*ATT_STRIDE;
    uint32_t* Vt = smA + 2*64*ATT_STRIDE;
    const uint32_t qsu = (uint32_t)__cvta_generic_to_shared(Qs);
    const uint32_t ksu = (uint32_t)__cvta_generic_to_shared(Ks);
    const uint32_t vsu = (uint32_t)__cvta_generic_to_shared(Vt);

    const int qb = blockIdx.x;
    const int nh = blockIdx.y;
    const int n  = nh / HH;
    const int hh = nh % HH;
    const int tid  = threadIdx.x;
    const int warp = tid >> 5;
    const int lane = tid & 31;
    const int g = lane >> 2, t = lane & 3;
    const int m0 = warp * 16;
    const int arow = lane & 15, acol = (lane >> 4) * 4;
    const int brow = (lane & 7) + ((lane >> 4) << 3), bcol = ((lane >> 3) & 1) * 4;

    // load Q tile (pre-scaled in projection); raw fp32 bits serve as tf32 operands
    #pragma unroll
    for (int f = 0; f < 8; f++) {
        int fid = tid + f * 128;
        int row = fid >> 4, c4 = fid & 15;
        uint4 a = *(const uint4*)(q + ((size_t)((qb*64+row)*NB + n)*EE + hh*DD + c4*4));
        *(uint4*)&Qs[row*ATT_STRIDE + c4*4] = a;
    }

    float m_i[2] = {-1e30f, -1e30f};
    float l_i[2] = {0.f, 0.f};
    float accO[8][4];
    #pragma unroll
    for (int dt = 0; dt < 8; dt++)
        #pragma unroll
        for (int r = 0; r < 4; r++) accO[dt][r] = 0.f;

    for (int jb = 0; jb <= qb; jb++) {
        __syncthreads();
        #pragma unroll
        for (int f = 0; f < 8; f++) {
            int fid = tid + f * 128;
            int row = fid >> 4, c4 = fid & 15;
            size_t goff = (size_t)((jb*64+row)*NB + n)*EE + hh*DD + c4*4;
            uint4 a = *(const uint4*)(k + goff);
            *(uint4*)&Ks[row*ATT_STRIDE + c4*4] = a;
            uint4 b = *(const uint4*)(v + goff);
            Vt[(c4*4+0)*ATT_STRIDE + row] = b.x;
            Vt[(c4*4+1)*ATT_STRIDE + row] = b.y;
            Vt[(c4*4+2)*ATT_STRIDE + row] = b.z;
            Vt[(c4*4+3)*ATT_STRIDE + row] = b.w;
        }
        __syncthreads();

        // S = Q K^T  (16 x 64 per warp)
        float sc[8][4];
        #pragma unroll
        for (int nt = 0; nt < 8; nt++)
            #pragma unroll
            for (int r = 0; r < 4; r++) sc[nt][r] = 0.f;

        #pragma unroll
        for (int kc = 0; kc < 8; kc++) {
            uint32_t a[4];
            ldsm4(a[0], a[1], a[2], a[3],
                  qsu + (unsigned)((m0 + arow)*ATT_STRIDE + kc*8 + acol) * 4);
            #pragma unroll
            for (int p = 0; p < 4; p++) {
                uint32_t r0, r1, r2, r3;
                ldsm4(r0, r1, r2, r3,
                      ksu + (unsigned)((p*16 + brow)*ATT_STRIDE + kc*8 + bcol) * 4);
                uint32_t b0[2] = {r0, r1}, b1[2] = {r2, r3};
                mma_tf32(sc[2*p],   a, b0);
                mma_tf32(sc[2*p+1], a, b1);
            }
        }

        // causal mask on diagonal tile
        if (jb == qb) {
            int r0 = m0 + g, r1 = m0 + g + 8;
            #pragma unroll
            for (int nt = 0; nt < 8; nt++) {
                int col = nt * 8 + t * 2;
                if (col     > r0) sc[nt][0] = -1e30f;
                if (col + 1 > r0) sc[nt][1] = -1e30f;
                if (col     > r1) sc[nt][2] = -1e30f;
                if (col + 1 > r1) sc[nt][3] = -1e30f;
            }
        }

        // online softmax (rows g, g+8; quad reduction)
        float mx0 = -1e30f, mx1 = -1e30f;
        #pragma unroll
        for (int nt = 0; nt < 8; nt++) {
            mx0 = fmaxf(mx0, fmaxf(sc[nt][0], sc[nt][1]));
            mx1 = fmaxf(mx1, fmaxf(sc[nt][2], sc[nt][3]));
        }
        #pragma unroll
        for (int off = 1; off < 4; off <<= 1) {
            mx0 = fmaxf(mx0, __shfl_xor_sync(0xffffffffu, mx0, off));
            mx1 = fmaxf(mx1, __shfl_xor_sync(0xffffffffu, mx1, off));
        }
        float mn0 = fmaxf(m_i[0], mx0), mn1 = fmaxf(m_i[1], mx1);
        float corr0 = __expf(m_i[0] - mn0), corr1 = __expf(m_i[1] - mn1);
        float sum0 = 0.f, sum1 = 0.f;
        #pragma unroll
        for (int nt = 0; nt < 8; nt++) {
            sc[nt][0] = __expf(sc[nt][0] - mn0); sum0 += sc[nt][0];
            sc[nt][1] = __expf(sc[nt][1] - mn0); sum0 += sc[nt][1];
            sc[nt][2] = __expf(sc[nt][2] - mn1); sum1 += sc[nt][2];
            sc[nt][3] = __expf(sc[nt][3] - mn1); sum1 += sc[nt][3];
        }
        #pragma unroll
        for (int off = 1; off < 4; off <<= 1) {
            sum0 += __shfl_xor_sync(0xffffffffu, sum0, off);
            sum1 += __shfl_xor_sync(0xffffffffu, sum1, off);
        }
        l_i[0] = l_i[0] * corr0 + sum0;
        l_i[1] = l_i[1] * corr1 + sum1;
        m_i[0] = mn0; m_i[1] = mn1;
        #pragma unroll
        for (int dt = 0; dt < 8; dt++) {
            accO[dt][0] *= corr0; accO[dt][1] *= corr0;
            accO[dt][2] *= corr1; accO[dt][3] *= corr1;
        }

        // O += P V  (P fragments via quad shuffles; raw bits as tf32)
        #pragma unroll
        for (int kc = 0; kc < 8; kc++) {
            const int bl   = lane & 28;
            const int src0 = bl | (t >> 1);
            const int src1 = src0 + 2;
            float u0 = __shfl_sync(0xffffffffu, sc[kc][0], src0);
            float u1 = __shfl_sync(0xffffffffu, sc[kc][1], src0);
            float w0 = __shfl_sync(0xffffffffu, sc[kc][0], src1);
            float w1 = __shfl_sync(0xffffffffu, sc[kc][1], src1);
            float x0 = __shfl_sync(0xffffffffu, sc[kc][2], src0);
            float x1 = __shfl_sync(0xffffffffu, sc[kc][3], src0);
            float y0 = __shfl_sync(0xffffffffu, sc[kc][2], src1);
            float y1 = __shfl_sync(0xffffffffu, sc[kc][3], src1);
            uint32_t a[4];
            a[0] = __float_as_uint((t & 1) ? u1 : u0);
            a[1] = __float_as_uint((t & 1) ? x1 : x0);
            a[2] = __float_as_uint((t & 1) ? w1 : w0);
            a[3] = __float_as_uint((t & 1) ? y1 : y0);
            #pragma unroll
            for (int p = 0; p < 4; p++) {
                uint32_t r0, r1, r2, r3;
                ldsm4(r0, r1, r2, r3,
                      vsu + (unsigned)((p*16 + brow)*ATT_STRIDE + kc*8 + bcol) * 4);
                uint32_t b0[2] = {r0, r1}, b1[2] = {r2, r3};
                mma_tf32(accO[2*p],   a, b0);
                mma_tf32(accO[2*p+1], a, b1);
            }
        }
    }

    // normalize + store
    float inv0 = 1.0f / l_i[0], inv1 = 1.0f / l_i[1];
    int l0 = qb*64 + m0 + g;
    int l1 = l0 + 8;
    #pragma unroll
    for (int dt = 0; dt < 8; dt++) {
        int d = hh*DD + dt*8 + t*2;
        *(float2*)(o + ((size_t)(l0*NB + n)*EE + d)) =
            make_float2(accO[dt][0]*inv0, accO[dt][1]*inv0);
        *(float2*)(o + ((size_t)(l1*NB + n)*EE + d)) =
            make_float2(accO[dt][2]*inv1, accO[dt][3]*inv1);
    }
}

// ---------------- launch ----------------
extern "C" void kernel_launch(void* const* d_in, const int* in_sizes, int n_in,
                              void* d_out, int out_size)
{
    const float* x     = (const float*)d_in[0];
    const float* ln1_w = (const float*)d_in[1];
    const float* ln1_b = (const float*)d_in[2];
    const float* wq    = (const float*)d_in[3];
    const float* bq    = (const float*)d_in[4];
    const float* wk    = (const float*)d_in[5];
    const float* bk    = (const float*)d_in[6];
    const float* wv    = (const float*)d_in[7];
    const float* bv    = (const float*)d_in[8];
    const float* wout  = (const float*)d_in[9];
    const float* bout  = (const float*)d_in[10];
    const float* ln2_w = (const float*)d_in[11];
    const float* ln2_b = (const float*)d_in[12];
    const float* fc1_w = (const float*)d_in[13];
    const float* fc1_b = (const float*)d_in[14];
    const float* fc2_w = (const float*)d_in[15];
    const float* fc2_b = (const float*)d_in[16];
    float* out = (float*)d_out;

    float *h, *q, *k, *v, *o, *x2, *h2, *mid;
    cudaGetSymbolAddress((void**)&h,   g_h);
    cudaGetSymbolAddress((void**)&q,   g_q);
    cudaGetSymbolAddress((void**)&k,   g_k);
    cudaGetSymbolAddress((void**)&v,   g_v);
    cudaGetSymbolAddress((void**)&o,   g_o);
    cudaGetSymbolAddress((void**)&x2,  g_x2);
    cudaGetSymbolAddress((void**)&h2,  g_h2);
    cudaGetSymbolAddress((void**)&mid, g_mid);

    cudaFuncSetAttribute(gemm_qkv,         cudaFuncAttributeMaxDynamicSharedMemorySize, GEMM_SMEM);
    cudaFuncSetAttribute(gemm_tc<EPI_RES>, cudaFuncAttributeMaxDynamicSharedMemorySize, GEMM_SMEM);
    cudaFuncSetAttribute(gemm_tc<EPI_GELU>,cudaFuncAttributeMaxDynamicSharedMemorySize, GEMM_SMEM);
    cudaFuncSetAttribute(attn_tc,          cudaFuncAttributeMaxDynamicSharedMemorySize, ATT_SMEM);

    // LN1
    ln_kernel<<<ROWS, 256>>>(x, ln1_w, ln1_b, h);

    // fused QKV projection (M=4096, N=3*1024, K=1024); scale fused into Q
    dim3 gqkv(3 * EE / 128, ROWS / 128);
    gemm_qkv<<<gqkv, 256, GEMM_SMEM>>>(h, wq, wk, wv, bq, bk, bv, q, k, v, EE);

    // causal flash attention (tf32 tensor cores)
    dim3 ga(LL / 64, NB * HH);
    attn_tc<<<ga, 128, ATT_SMEM>>>(q, k, v, o);

    // out projection + residual(x)
    dim3 g1024(EE / 128, ROWS / 128);
    gemm_tc<EPI_RES><<<g1024, 256, GEMM_SMEM>>>(o, wout, bout, x, x2, EE, EE);

    // LN2
    ln_kernel<<<ROWS, 256>>>(x2, ln2_w, ln2_b, h2);

    // FC1 + GELU (M=4096, N=4096, K=1024)
    dim3 g4096(FF / 128, ROWS / 128);
    gemm_tc<EPI_GELU><<<g4096, 256, GEMM_SMEM>>>(h2, fc1_w, fc1_b, nullptr, mid, FF, EE);

    // FC2 + residual(x2) -> out (M=4096, N=1024, K=4096)
    gemm_tc<EPI_RES><<<g1024, 256, GEMM_SMEM>>>(mid, fc2_w, fc2_b, x2, out, EE, FF);
}

// round 5
// speedup vs baseline: 5.6120x; 1.7887x over previous
#include <cuda_runtime.h>
#include <cuda_fp16.h>
#include <math.h>
#include <stdint.h>

// Problem constants
#define LL 2048
#define NB 2
#define EE 1024
#define HH 16
#define DD 64
#define FF 4096
#define ROWS (LL*NB)   // 4096

// ---------------- scratch (no allocation allowed) ----------------
__device__ __half g_h  [ROWS*EE];
__device__ __half g_q  [ROWS*EE];
__device__ __half g_k  [ROWS*EE];
__device__ __half g_v  [ROWS*EE];
__device__ __half g_o  [ROWS*EE];
__device__ __half g_h2 [ROWS*EE];
__device__ __half g_mid[(size_t)ROWS*FF];
__device__ float  g_x2 [ROWS*EE];
// fp16 weight copies
__device__ __half g_wq [EE*EE];
__device__ __half g_wk [EE*EE];
__device__ __half g_wv [EE*EE];
__device__ __half g_wo [EE*EE];
__device__ __half g_w1 [FF*EE];
__device__ __half g_w2 [EE*FF];

// ---------------- helpers ----------------
__device__ __forceinline__ uint32_t h2pack(float a, float b) {
    __half2 h = __floats2half2_rn(a, b);
    return *reinterpret_cast<uint32_t*>(&h);
}
__device__ __forceinline__ void mma_f16(float* c, const uint32_t* a, const uint32_t* b) {
    asm volatile(
        "mma.sync.aligned.m16n8k16.row.col.f32.f16.f16.f32 "
        "{%0,%1,%2,%3}, {%4,%5,%6,%7}, {%8,%9}, {%0,%1,%2,%3};\n"
        : "+f"(c[0]), "+f"(c[1]), "+f"(c[2]), "+f"(c[3])
        : "r"(a[0]), "r"(a[1]), "r"(a[2]), "r"(a[3]), "r"(b[0]), "r"(b[1]));
}
__device__ __forceinline__ void ldsm4(uint32_t& r0, uint32_t& r1, uint32_t& r2, uint32_t& r3,
                                      uint32_t addr) {
    asm volatile("ldmatrix.sync.aligned.m8n8.x4.shared.b16 {%0,%1,%2,%3}, [%4];\n"
                 : "=r"(r0), "=r"(r1), "=r"(r2), "=r"(r3) : "r"(addr));
}
__device__ __forceinline__ void cp16(uint32_t saddr, const void* g) {
    asm volatile("cp.async.cg.shared.global [%0], [%1], 16;\n" :: "r"(saddr), "l"(g));
}
#define CP_COMMIT asm volatile("cp.async.commit_group;\n")
#define CP_WAIT1  asm volatile("cp.async.wait_group 1;\n")

__device__ __forceinline__ float gelu_exact(float t) {
    return 0.5f * t * (1.0f + erff(t * 0.70710678118654752f));
}

// ---------------- fp32 -> fp16 conversion (weights) ----------------
__global__ __launch_bounds__(256)
void f2h_kernel(const float4* __restrict__ src, uint32_t* __restrict__ dst, int n4)
{
    int i = blockIdx.x * 256 + threadIdx.x;
    if (i < n4) {
        float4 v = src[i];
        dst[2*i]   = h2pack(v.x, v.y);
        dst[2*i+1] = h2pack(v.z, v.w);
    }
}

// ---------------- LayerNorm: fp32 in, fp16 out ----------------
__global__ __launch_bounds__(256)
void ln_kernel(const float* __restrict__ x, const float* __restrict__ w,
               const float* __restrict__ b, __half* __restrict__ out)
{
    int row = blockIdx.x;
    int tid = threadIdx.x;
    const float4* xr = (const float4*)(x + (size_t)row * EE);
    float4 v = xr[tid];
    float s  = v.x + v.y + v.z + v.w;
    float ss = v.x*v.x + v.y*v.y + v.z*v.z + v.w*v.w;
    #pragma unroll
    for (int o = 16; o > 0; o >>= 1) {
        s  += __shfl_xor_sync(0xffffffffu, s,  o);
        ss += __shfl_xor_sync(0xffffffffu, ss, o);
    }
    __shared__ float sbuf[8], ssbuf[8];
    if ((tid & 31) == 0) { sbuf[tid >> 5] = s; ssbuf[tid >> 5] = ss; }
    __syncthreads();
    float ts = 0.f, tss = 0.f;
    #pragma unroll
    for (int i = 0; i < 8; i++) { ts += sbuf[i]; tss += ssbuf[i]; }
    float mean = ts * (1.0f / EE);
    float var  = tss * (1.0f / EE) - mean * mean;
    float inv  = rsqrtf(var + 1e-5f);
    float4 w4 = ((const float4*)w)[tid];
    float4 b4 = ((const float4*)b)[tid];
    uint32_t* orow = (uint32_t*)(out + (size_t)row * EE);
    orow[2*tid]   = h2pack((v.x - mean)*inv*w4.x + b4.x, (v.y - mean)*inv*w4.y + b4.y);
    orow[2*tid+1] = h2pack((v.z - mean)*inv*w4.z + b4.z, (v.w - mean)*inv*w4.w + b4.w);
}

// ---------------- fp16 GEMM core, 3-stage cp.async pipeline ----------------
// C[m][n] = sum_k A[m][k]*B[n][k]. BM=BN=128, BK=64 halves, 8 warps (2x4).
#define KST 72                       // halves per smem row (144 B)
#define AST_BYTES (128*KST*2)        // 18432
#define STAGE_BYTES (2*AST_BYTES)    // 36864 (A+B)
#define NSTAGE 3
#define GEMM_SMEM (NSTAGE*STAGE_BYTES)   // 110592

__device__ __forceinline__ void issue_tile(uint32_t smu, const __half* A, const __half* B,
                                           int bm, int bn, int K, int k0, int slot)
{
    const int tid = threadIdx.x;
    uint32_t ao = smu + (unsigned)slot * STAGE_BYTES;
    uint32_t bo = ao + AST_BYTES;
    #pragma unroll
    for (int c = 0; c < 4; c++) {
        int cid = tid + c * 256;
        int row = cid >> 2;
        int kc  = (cid & 3) * 16;     // halves, 4 chunks of 8 halves... (16B = 8 halves)
        // 64 halves per row = 4 chunks of 8 halves? -> (cid&3)*8? No: 8 halves per cp16.
        (void)kc;
    }
    // correct mapping: 128 rows x 64 halves = 1024 chunks of 8 halves
    #pragma unroll
    for (int c = 0; c < 4; c++) {
        int cid = tid + c * 256;
        int row = cid >> 3;
        int kc  = (cid & 7) * 8;
        cp16(ao + (unsigned)(row*KST + kc)*2, A + (size_t)(bm+row)*K + k0 + kc);
        cp16(bo + (unsigned)(row*KST + kc)*2, B + (size_t)(bn+row)*K + k0 + kc);
    }
}

__device__ __forceinline__ void gemm_main(const __half* __restrict__ A,
                                          const __half* __restrict__ B,
                                          int bm, int bn, int K, uint32_t smu,
                                          float c[4][4][4])
{
    const int tid  = threadIdx.x;
    const int warp = tid >> 5;
    const int lane = tid & 31;
    const int wm = (warp >> 2) * 64;
    const int wn = (warp & 3) * 32;
    const int ar = lane & 15;                       // A ldsm row-in-tile
    const int ac = (lane >> 4) * 8;                 // A ldsm col (halves)
    const int br = (lane & 7) + ((lane >> 4) << 3); // B ldsm row-in-tile
    const int bc = ((lane >> 3) & 1) * 8;           // B ldsm col (halves)

    #pragma unroll
    for (int mt = 0; mt < 4; mt++)
        #pragma unroll
        for (int nt = 0; nt < 4; nt++)
            #pragma unroll
            for (int r = 0; r < 4; r++) c[mt][nt][r] = 0.f;

    const int NT = K >> 6;   // BK = 64
    issue_tile(smu, A, B, bm, bn, K, 0,  0); CP_COMMIT;
    issue_tile(smu, A, B, bm, bn, K, 64, 1); CP_COMMIT;

    for (int kt = 0; kt < NT; kt++) {
        CP_WAIT1;
        __syncthreads();
        if (kt + 2 < NT) issue_tile(smu, A, B, bm, bn, K, (kt+2) << 6, (kt+2) % NSTAGE);
        CP_COMMIT;

        const uint32_t sa = smu + (unsigned)(kt % NSTAGE) * STAGE_BYTES;
        const uint32_t sb = sa + AST_BYTES;

        #pragma unroll
        for (int kc = 0; kc < 4; kc++) {
            uint32_t a[4][4];
            #pragma unroll
            for (int mt = 0; mt < 4; mt++)
                ldsm4(a[mt][0], a[mt][1], a[mt][2], a[mt][3],
                      sa + (unsigned)((wm + mt*16 + ar)*KST + kc*16 + ac) * 2);
            uint32_t bf[4][2];
            #pragma unroll
            for (int p = 0; p < 2; p++) {
                uint32_t r0, r1, r2, r3;
                ldsm4(r0, r1, r2, r3,
                      sb + (unsigned)((wn + p*16 + br)*KST + kc*16 + bc) * 2);
                bf[2*p][0]   = r0; bf[2*p][1]   = r1;
                bf[2*p+1][0] = r2; bf[2*p+1][1] = r3;
            }
            #pragma unroll
            for (int mt = 0; mt < 4; mt++)
                #pragma unroll
                for (int nt = 0; nt < 4; nt++)
                    mma_f16(c[mt][nt], a[mt], bf[nt]);
        }
    }
}

// ---------------- GEMM with fp32 output + residual ----------------
__global__ __launch_bounds__(256, 2)
void gemm_res(const __half* __restrict__ A, const __half* __restrict__ B,
              const float* __restrict__ bias, const float* __restrict__ res,
              float* __restrict__ C, int Nn, int K)
{
    extern __shared__ uint32_t smg[];
    uint32_t smu = (uint32_t)__cvta_generic_to_shared(smg);
    const int bm = blockIdx.y * 128;
    const int bn = blockIdx.x * 128;
    float c[4][4][4];
    gemm_main(A, B, bm, bn, K, smu, c);

    const int tid = threadIdx.x, warp = tid >> 5, lane = tid & 31;
    const int g = lane >> 2, t = lane & 3;
    const int wm = (warp >> 2) * 64, wn = (warp & 3) * 32;
    #pragma unroll
    for (int mt = 0; mt < 4; mt++) {
        #pragma unroll
        for (int nt = 0; nt < 4; nt++) {
            int col = bn + wn + nt * 8 + t * 2;
            float2 bi = *(const float2*)(bias + col);
            #pragma unroll
            for (int h = 0; h < 2; h++) {
                int row = bm + wm + mt * 16 + g + h * 8;
                float2 r = *(const float2*)(res + (size_t)row * Nn + col);
                *(float2*)(C + (size_t)row * Nn + col) =
                    make_float2(c[mt][nt][h*2+0] + bi.x + r.x,
                                c[mt][nt][h*2+1] + bi.y + r.y);
            }
        }
    }
}

// ---------------- GEMM with GELU + fp16 output ----------------
__global__ __launch_bounds__(256, 2)
void gemm_gelu(const __half* __restrict__ A, const __half* __restrict__ B,
               const float* __restrict__ bias, __half* __restrict__ C, int Nn, int K)
{
    extern __shared__ uint32_t smg[];
    uint32_t smu = (uint32_t)__cvta_generic_to_shared(smg);
    const int bm = blockIdx.y * 128;
    const int bn = blockIdx.x * 128;
    float c[4][4][4];
    gemm_main(A, B, bm, bn, K, smu, c);

    const int tid = threadIdx.x, warp = tid >> 5, lane = tid & 31;
    const int g = lane >> 2, t = lane & 3;
    const int wm = (warp >> 2) * 64, wn = (warp & 3) * 32;
    #pragma unroll
    for (int mt = 0; mt < 4; mt++) {
        #pragma unroll
        for (int nt = 0; nt < 4; nt++) {
            int col = bn + wn + nt * 8 + t * 2;
            float2 bi = *(const float2*)(bias + col);
            #pragma unroll
            for (int h = 0; h < 2; h++) {
                int row = bm + wm + mt * 16 + g + h * 8;
                *(uint32_t*)(C + (size_t)row * Nn + col) =
                    h2pack(gelu_exact(c[mt][nt][h*2+0] + bi.x),
                           gelu_exact(c[mt][nt][h*2+1] + bi.y));
            }
        }
    }
}

// ---------------- fused QKV projection (fp16 out, scale on Q) ----------------
__global__ __launch_bounds__(256, 2)
void gemm_qkv(const __half* __restrict__ A,
              const __half* __restrict__ Bq, const __half* __restrict__ Bk, const __half* __restrict__ Bv,
              const float* __restrict__ bq, const float* __restrict__ bk, const float* __restrict__ bv,
              __half* __restrict__ Cq, __half* __restrict__ Ck, __half* __restrict__ Cv, int K)
{
    extern __shared__ uint32_t smg[];
    uint32_t smu = (uint32_t)__cvta_generic_to_shared(smg);
    const int bm  = blockIdx.y * 128;
    const int bng = blockIdx.x * 128;
    const int seg = bng >> 10;
    const int bn  = bng & 1023;
    const __half* B   = (seg == 0) ? Bq : (seg == 1) ? Bk : Bv;
    const float* bias = (seg == 0) ? bq : (seg == 1) ? bk : bv;
    __half*      C    = (seg == 0) ? Cq : (seg == 1) ? Ck : Cv;
    const float scale = (seg == 0) ? 0.125f : 1.0f;

    float c[4][4][4];
    gemm_main(A, B, bm, bn, K, smu, c);

    const int tid = threadIdx.x, warp = tid >> 5, lane = tid & 31;
    const int g = lane >> 2, t = lane & 3;
    const int wm = (warp >> 2) * 64, wn = (warp & 3) * 32;
    #pragma unroll
    for (int mt = 0; mt < 4; mt++) {
        #pragma unroll
        for (int nt = 0; nt < 4; nt++) {
            int col = bn + wn + nt * 8 + t * 2;
            float2 bi = *(const float2*)(bias + col);
            #pragma unroll
            for (int h = 0; h < 2; h++) {
                int row = bm + wm + mt * 16 + g + h * 8;
                *(uint32_t*)(C + (size_t)row * 1024 + col) =
                    h2pack((c[mt][nt][h*2+0] + bi.x) * scale,
                           (c[mt][nt][h*2+1] + bi.y) * scale);
            }
        }
    }
}

// ---------------- flash attention, fp16 MMA ----------------
// Br=Bc=64, 128 threads (4 warps); warp tile 16 q-rows x 64 keys.
#define ATST 72   // halves per smem row

__global__ __launch_bounds__(128)
void attn_h(const __half* __restrict__ q, const __half* __restrict__ k,
            const __half* __restrict__ v, __half* __restrict__ o)
{
    __shared__ __half Qs[64*ATST];
    __shared__ __half Ks[64*ATST];
    __shared__ __half Vt[64*ATST];   // [d][key]
    const uint32_t qsu = (uint32_t)__cvta_generic_to_shared(Qs);
    const uint32_t ksu = (uint32_t)__cvta_generic_to_shared(Ks);
    const uint32_t vsu = (uint32_t)__cvta_generic_to_shared(Vt);

    const int qb = blockIdx.x;
    const int nh = blockIdx.y;
    const int n  = nh / HH;
    const int hh = nh % HH;
    const int tid  = threadIdx.x;
    const int warp = tid >> 5;
    const int lane = tid & 31;
    const int g = lane >> 2, t = lane & 3;
    const int m0 = warp * 16;
    const int ar = lane & 15, ac = (lane >> 4) * 8;
    const int br = (lane & 7) + ((lane >> 4) << 3), bc = ((lane >> 3) & 1) * 8;

    // Q tile: [row][d], fp16 (pre-scaled)
    #pragma unroll
    for (int p = 0; p < 4; p++) {
        int idx = tid + p * 128;            // 512 chunks of 8 halves
        int row = idx >> 3, c8 = (idx & 7) * 8;
        *(uint4*)&Qs[row*ATST + c8] =
            *(const uint4*)(q + ((size_t)((qb*64+row)*NB + n)*EE + hh*DD + c8));
    }

    float m_i[2] = {-1e30f, -1e30f};
    float l_i[2] = {0.f, 0.f};
    float accO[8][4];
    #pragma unroll
    for (int dt = 0; dt < 8; dt++)
        #pragma unroll
        for (int r = 0; r < 4; r++) accO[dt][r] = 0.f;

    for (int jb = 0; jb <= qb; jb++) {
        __syncthreads();
        // K: [key][d]; V transposed: Vt[d][key]
        #pragma unroll
        for (int p = 0; p < 4; p++) {
            int idx = tid + p * 128;
            int row = idx >> 3, c8 = (idx & 7) * 8;
            *(uint4*)&Ks[row*ATST + c8] =
                *(const uint4*)(k + ((size_t)((jb*64+row)*NB + n)*EE + hh*DD + c8));
            int key = idx & 63, dc = (idx >> 6) * 8;
            uint4 b = *(const uint4*)(v + ((size_t)((jb*64+key)*NB + n)*EE + hh*DD + dc));
            const __half* hb = (const __half*)&b;
            #pragma unroll
            for (int j = 0; j < 8; j++) Vt[(dc+j)*ATST + key] = hb[j];
        }
        __syncthreads();

        // S = Q K^T (16 x 64 per warp)
        float sc[8][4];
        #pragma unroll
        for (int nt = 0; nt < 8; nt++)
            #pragma unroll
            for (int r = 0; r < 4; r++) sc[nt][r] = 0.f;

        #pragma unroll
        for (int kc = 0; kc < 4; kc++) {
            uint32_t a[4];
            ldsm4(a[0], a[1], a[2], a[3],
                  qsu + (unsigned)((m0 + ar)*ATST + kc*16 + ac) * 2);
            #pragma unroll
            for (int p = 0; p < 4; p++) {
                uint32_t r0, r1, r2, r3;
                ldsm4(r0, r1, r2, r3,
                      ksu + (unsigned)((p*16 + br)*ATST + kc*16 + bc) * 2);
                uint32_t b0[2] = {r0, r1}, b1[2] = {r2, r3};
                mma_f16(sc[2*p],   a, b0);
                mma_f16(sc[2*p+1], a, b1);
            }
        }

        // causal mask on diagonal tile
        if (jb == qb) {
            int r0 = m0 + g, r1 = m0 + g + 8;
            #pragma unroll
            for (int nt = 0; nt < 8; nt++) {
                int col = nt * 8 + t * 2;
                if (col     > r0) sc[nt][0] = -1e30f;
                if (col + 1 > r0) sc[nt][1] = -1e30f;
                if (col     > r1) sc[nt][2] = -1e30f;
                if (col + 1 > r1) sc[nt][3] = -1e30f;
            }
        }

        // online softmax (rows g, g+8; quad reduction)
        float mx0 = -1e30f, mx1 = -1e30f;
        #pragma unroll
        for (int nt = 0; nt < 8; nt++) {
            mx0 = fmaxf(mx0, fmaxf(sc[nt][0], sc[nt][1]));
            mx1 = fmaxf(mx1, fmaxf(sc[nt][2], sc[nt][3]));
        }
        #pragma unroll
        for (int off = 1; off < 4; off <<= 1) {
            mx0 = fmaxf(mx0, __shfl_xor_sync(0xffffffffu, mx0, off));
            mx1 = fmaxf(mx1, __shfl_xor_sync(0xffffffffu, mx1, off));
        }
        float mn0 = fmaxf(m_i[0], mx0), mn1 = fmaxf(m_i[1], mx1);
        float corr0 = __expf(m_i[0] - mn0), corr1 = __expf(m_i[1] - mn1);
        float sum0 = 0.f, sum1 = 0.f;
        #pragma unroll
        for (int nt = 0; nt < 8; nt++) {
            sc[nt][0] = __expf(sc[nt][0] - mn0); sum0 += sc[nt][0];
            sc[nt][1] = __expf(sc[nt][1] - mn0); sum0 += sc[nt][1];
            sc[nt][2] = __expf(sc[nt][2] - mn1); sum1 += sc[nt][2];
            sc[nt][3] = __expf(sc[nt][3] - mn1); sum1 += sc[nt][3];
        }
        #pragma unroll
        for (int off = 1; off < 4; off <<= 1) {
            sum0 += __shfl_xor_sync(0xffffffffu, sum0, off);
            sum1 += __shfl_xor_sync(0xffffffffu, sum1, off);
        }
        l_i[0] = l_i[0] * corr0 + sum0;
        l_i[1] = l_i[1] * corr1 + sum1;
        m_i[0] = mn0; m_i[1] = mn1;
        #pragma unroll
        for (int dt = 0; dt < 8; dt++) {
            accO[dt][0] *= corr0; accO[dt][1] *= corr0;
            accO[dt][2] *= corr1; accO[dt][3] *= corr1;
        }

        // O += P V: S C-frag IS the P A-frag for m16n8k16 (no shuffles)
        #pragma unroll
        for (int kc = 0; kc < 4; kc++) {
            uint32_t a[4];
            a[0] = h2pack(sc[2*kc][0],   sc[2*kc][1]);     // m=g,   k low
            a[1] = h2pack(sc[2*kc][2],   sc[2*kc][3]);     // m=g+8, k low
            a[2] = h2pack(sc[2*kc+1][0], sc[2*kc+1][1]);   // m=g,   k high
            a[3] = h2pack(sc[2*kc+1][2], sc[2*kc+1][3]);   // m=g+8, k high
            #pragma unroll
            for (int p = 0; p < 4; p++) {
                uint32_t r0, r1, r2, r3;
                ldsm4(r0, r1, r2, r3,
                      vsu + (unsigned)((p*16 + br)*ATST + kc*16 + bc) * 2);
                uint32_t b0[2] = {r0, r1}, b1[2] = {r2, r3};
                mma_f16(accO[2*p],   a, b0);
                mma_f16(accO[2*p+1], a, b1);
            }
        }
    }

    // normalize + store fp16
    float inv0 = 1.0f / l_i[0], inv1 = 1.0f / l_i[1];
    int l0 = qb*64 + m0 + g;
    int l1 = l0 + 8;
    #pragma unroll
    for (int dt = 0; dt < 8; dt++) {
        int d = hh*DD + dt*8 + t*2;
        *(uint32_t*)(o + ((size_t)(l0*NB + n)*EE + d)) =
            h2pack(accO[dt][0]*inv0, accO[dt][1]*inv0);
        *(uint32_t*)(o + ((size_t)(l1*NB + n)*EE + d)) =
            h2pack(accO[dt][2]*inv1, accO[dt][3]*inv1);
    }
}

// ---------------- launch ----------------
extern "C" void kernel_launch(void* const* d_in, const int* in_sizes, int n_in,
                              void* d_out, int out_size)
{
    const float* x     = (const float*)d_in[0];
    const float* ln1_w = (const float*)d_in[1];
    const float* ln1_b = (const float*)d_in[2];
    const float* wq    = (const float*)d_in[3];
    const float* bq    = (const float*)d_in[4];
    const float* wk    = (const float*)d_in[5];
    const float* bk    = (const float*)d_in[6];
    const float* wv    = (const float*)d_in[7];
    const float* bv    = (const float*)d_in[8];
    const float* wout  = (const float*)d_in[9];
    const float* bout  = (const float*)d_in[10];
    const float* ln2_w = (const float*)d_in[11];
    const float* ln2_b = (const float*)d_in[12];
    const float* fc1_w = (const float*)d_in[13];
    const float* fc1_b = (const float*)d_in[14];
    const float* fc2_w = (const float*)d_in[15];
    const float* fc2_b = (const float*)d_in[16];
    float* out = (float*)d_out;

    __half *h, *q, *k, *v, *o, *h2, *mid;
    __half *cwq, *cwk, *cwv, *cwo, *cw1, *cw2;
    float  *x2;
    cudaGetSymbolAddress((void**)&h,   g_h);
    cudaGetSymbolAddress((void**)&q,   g_q);
    cudaGetSymbolAddress((void**)&k,   g_k);
    cudaGetSymbolAddress((void**)&v,   g_v);
    cudaGetSymbolAddress((void**)&o,   g_o);
    cudaGetSymbolAddress((void**)&h2,  g_h2);
    cudaGetSymbolAddress((void**)&mid, g_mid);
    cudaGetSymbolAddress((void**)&x2,  g_x2);
    cudaGetSymbolAddress((void**)&cwq, g_wq);
    cudaGetSymbolAddress((void**)&cwk, g_wk);
    cudaGetSymbolAddress((void**)&cwv, g_wv);
    cudaGetSymbolAddress((void**)&cwo, g_wo);
    cudaGetSymbolAddress((void**)&cw1, g_w1);
    cudaGetSymbolAddress((void**)&cw2, g_w2);

    cudaFuncSetAttribute(gemm_qkv,  cudaFuncAttributeMaxDynamicSharedMemorySize, GEMM_SMEM);
    cudaFuncSetAttribute(gemm_res,  cudaFuncAttributeMaxDynamicSharedMemorySize, GEMM_SMEM);
    cudaFuncSetAttribute(gemm_gelu, cudaFuncAttributeMaxDynamicSharedMemorySize, GEMM_SMEM);

    // weight conversions (fp32 -> fp16)
    f2h_kernel<<<(EE*EE/4 + 255)/256, 256>>>((const float4*)wq,    (uint32_t*)cwq, EE*EE/4);
    f2h_kernel<<<(EE*EE/4 + 255)/256, 256>>>((const float4*)wk,    (uint32_t*)cwk, EE*EE/4);
    f2h_kernel<<<(EE*EE/4 + 255)/256, 256>>>((const float4*)wv,    (uint32_t*)cwv, EE*EE/4);
    f2h_kernel<<<(EE*EE/4 + 255)/256, 256>>>((const float4*)wout,  (uint32_t*)cwo, EE*EE/4);
    f2h_kernel<<<(FF*EE/4 + 255)/256, 256>>>((const float4*)fc1_w, (uint32_t*)cw1, FF*EE/4);
    f2h_kernel<<<(FF*EE/4 + 255)/256, 256>>>((const float4*)fc2_w, (uint32_t*)cw2, FF*EE/4);

    // LN1: x -> h (fp16)
    ln_kernel<<<ROWS, 256>>>(x, ln1_w, ln1_b, h);

    // fused QKV (M=4096, N=3*1024, K=1024); scale folded into Q
    dim3 gqkv(3 * EE / 128, ROWS / 128);
    gemm_qkv<<<gqkv, 256, GEMM_SMEM>>>(h, cwq, cwk, cwv, bq, bk, bv, q, k, v, EE);

    // causal flash attention (fp16 MMA)
    dim3 ga(LL / 64, NB * HH);
    attn_h<<<ga, 128>>>(q, k, v, o);

    // out projection + residual(x) -> x2 (fp32)
    dim3 g1024(EE / 128, ROWS / 128);
    gemm_res<<<g1024, 256, GEMM_SMEM>>>(o, cwo, bout, x, x2, EE, EE);

    // LN2: x2 -> h2 (fp16)
    ln_kernel<<<ROWS, 256>>>(x2, ln2_w, ln2_b, h2);

    // FC1 + GELU -> mid (fp16)
    dim3 g4096(FF / 128, ROWS / 128);
    gemm_gelu<<<g4096, 256, GEMM_SMEM>>>(h2, cw1, fc1_b, mid, FF, EE);

    // FC2 + residual(x2) -> out (fp32)
    gemm_res<<<g1024, 256, GEMM_SMEM>>>(mid, cw2, fc2_b, x2, out, EE, FF);
}

// round 6
// speedup vs baseline: 6.1203x; 1.0906x over previous
#include <cuda_runtime.h>
#include <cuda_fp16.h>
#include <math.h>
#include <stdint.h>

// Problem constants
#define LL 2048
#define NB 2
#define EE 1024
#define HH 16
#define DD 64
#define FF 4096
#define ROWS (LL*NB)   // 4096

// ---------------- scratch (no allocation allowed) ----------------
__device__ __half g_h  [ROWS*EE];
__device__ __half g_q  [ROWS*EE];
__device__ __half g_k  [ROWS*EE];
__device__ __half g_v  [ROWS*EE];
__device__ __half g_o  [ROWS*EE];
__device__ __half g_h2 [ROWS*EE];
__device__ __half g_mid[(size_t)ROWS*FF];
__device__ float  g_x2 [ROWS*EE];
// fp16 weight copies
__device__ __half g_wq [EE*EE];
__device__ __half g_wk [EE*EE];
__device__ __half g_wv [EE*EE];
__device__ __half g_wo [EE*EE];
__device__ __half g_w1 [FF*EE];
__device__ __half g_w2 [EE*FF];

// ---------------- helpers ----------------
__device__ __forceinline__ uint32_t h2pack(float a, float b) {
    __half2 h = __floats2half2_rn(a, b);
    return *reinterpret_cast<uint32_t*>(&h);
}
__device__ __forceinline__ void mma_f16(float* c, const uint32_t* a, const uint32_t* b) {
    asm volatile(
        "mma.sync.aligned.m16n8k16.row.col.f32.f16.f16.f32 "
        "{%0,%1,%2,%3}, {%4,%5,%6,%7}, {%8,%9}, {%0,%1,%2,%3};\n"
        : "+f"(c[0]), "+f"(c[1]), "+f"(c[2]), "+f"(c[3])
        : "r"(a[0]), "r"(a[1]), "r"(a[2]), "r"(a[3]), "r"(b[0]), "r"(b[1]));
}
__device__ __forceinline__ void ldsm4(uint32_t& r0, uint32_t& r1, uint32_t& r2, uint32_t& r3,
                                      uint32_t addr) {
    asm volatile("ldmatrix.sync.aligned.m8n8.x4.shared.b16 {%0,%1,%2,%3}, [%4];\n"
                 : "=r"(r0), "=r"(r1), "=r"(r2), "=r"(r3) : "r"(addr));
}
__device__ __forceinline__ void ldsm4t(uint32_t& r0, uint32_t& r1, uint32_t& r2, uint32_t& r3,
                                       uint32_t addr) {
    asm volatile("ldmatrix.sync.aligned.m8n8.x4.trans.shared.b16 {%0,%1,%2,%3}, [%4];\n"
                 : "=r"(r0), "=r"(r1), "=r"(r2), "=r"(r3) : "r"(addr));
}
__device__ __forceinline__ void cp16(uint32_t saddr, const void* g) {
    asm volatile("cp.async.cg.shared.global [%0], [%1], 16;\n" :: "r"(saddr), "l"(g));
}
#define CP_COMMIT asm volatile("cp.async.commit_group;\n")
#define CP_WAIT1  asm volatile("cp.async.wait_group 1;\n")

__device__ __forceinline__ float gelu_exact(float t) {
    return 0.5f * t * (1.0f + erff(t * 0.70710678118654752f));
}

// ---------------- fused fp32 -> fp16 weight conversion (single launch) ----------------
// segments (float4 units): wq,wk,wv,wo = 262144 each; fc1,fc2 = 1048576 each.
__global__ __launch_bounds__(256)
void f2h_all(const float4* __restrict__ wq, const float4* __restrict__ wk,
             const float4* __restrict__ wv, const float4* __restrict__ wo,
             const float4* __restrict__ w1, const float4* __restrict__ w2,
             uint32_t* __restrict__ dq, uint32_t* __restrict__ dk,
             uint32_t* __restrict__ dv, uint32_t* __restrict__ do_,
             uint32_t* __restrict__ d1, uint32_t* __restrict__ d2)
{
    int i = blockIdx.x * 256 + threadIdx.x;   // 0 .. 3145727
    const float4* s; uint32_t* d; int local;
    if (i < 1048576) {
        int w = i >> 18;                       // 0..3
        local = i & 262143;
        s = (w == 0) ? wq : (w == 1) ? wk : (w == 2) ? wv : wo;
        d = (w == 0) ? dq : (w == 1) ? dk : (w == 2) ? dv : do_;
    } else if (i < 2097152) {
        local = i - 1048576; s = w1; d = d1;
    } else {
        local = i - 2097152; s = w2; d = d2;
    }
    float4 v = s[local];
    d[2*local]   = h2pack(v.x, v.y);
    d[2*local+1] = h2pack(v.z, v.w);
}

// ---------------- LayerNorm: fp32 in, fp16 out ----------------
__global__ __launch_bounds__(256)
void ln_kernel(const float* __restrict__ x, const float* __restrict__ w,
               const float* __restrict__ b, __half* __restrict__ out)
{
    int row = blockIdx.x;
    int tid = threadIdx.x;
    const float4* xr = (const float4*)(x + (size_t)row * EE);
    float4 v = xr[tid];
    float s  = v.x + v.y + v.z + v.w;
    float ss = v.x*v.x + v.y*v.y + v.z*v.z + v.w*v.w;
    #pragma unroll
    for (int o = 16; o > 0; o >>= 1) {
        s  += __shfl_xor_sync(0xffffffffu, s,  o);
        ss += __shfl_xor_sync(0xffffffffu, ss, o);
    }
    __shared__ float sbuf[8], ssbuf[8];
    if ((tid & 31) == 0) { sbuf[tid >> 5] = s; ssbuf[tid >> 5] = ss; }
    __syncthreads();
    float ts = 0.f, tss = 0.f;
    #pragma unroll
    for (int i = 0; i < 8; i++) { ts += sbuf[i]; tss += ssbuf[i]; }
    float mean = ts * (1.0f / EE);
    float var  = tss * (1.0f / EE) - mean * mean;
    float inv  = rsqrtf(var + 1e-5f);
    float4 w4 = ((const float4*)w)[tid];
    float4 b4 = ((const float4*)b)[tid];
    uint32_t* orow = (uint32_t*)(out + (size_t)row * EE);
    orow[2*tid]   = h2pack((v.x - mean)*inv*w4.x + b4.x, (v.y - mean)*inv*w4.y + b4.y);
    orow[2*tid+1] = h2pack((v.z - mean)*inv*w4.z + b4.z, (v.w - mean)*inv*w4.w + b4.w);
}

// ---------------- fp16 GEMM core, 3-stage cp.async pipeline ----------------
// C[m][n] = sum_k A[m][k]*B[n][k]. BM=BN=128, BK=64 halves, 8 warps (2x4).
#define KST 72                       // halves per smem row (144 B)
#define AST_BYTES (128*KST*2)        // 18432
#define STAGE_BYTES (2*AST_BYTES)    // 36864 (A+B)
#define NSTAGE 3
#define GEMM_SMEM (NSTAGE*STAGE_BYTES)   // 110592

__device__ __forceinline__ void issue_tile(uint32_t smu, const __half* A, const __half* B,
                                           int bm, int bn, int K, int k0, int slot)
{
    const int tid = threadIdx.x;
    uint32_t ao = smu + (unsigned)slot * STAGE_BYTES;
    uint32_t bo = ao + AST_BYTES;
    // 128 rows x 64 halves = 1024 chunks of 8 halves (16B) per operand
    #pragma unroll
    for (int c = 0; c < 4; c++) {
        int cid = tid + c * 256;
        int row = cid >> 3;
        int kc  = (cid & 7) * 8;
        cp16(ao + (unsigned)(row*KST + kc)*2, A + (size_t)(bm+row)*K + k0 + kc);
        cp16(bo + (unsigned)(row*KST + kc)*2, B + (size_t)(bn+row)*K + k0 + kc);
    }
}

__device__ __forceinline__ void gemm_main(const __half* __restrict__ A,
                                          const __half* __restrict__ B,
                                          int bm, int bn, int K, uint32_t smu,
                                          float c[4][4][4])
{
    const int tid  = threadIdx.x;
    const int warp = tid >> 5;
    const int lane = tid & 31;
    const int wm = (warp >> 2) * 64;
    const int wn = (warp & 3) * 32;
    const int ar = lane & 15;
    const int ac = (lane >> 4) * 8;
    const int br = (lane & 7) + ((lane >> 4) << 3);
    const int bc = ((lane >> 3) & 1) * 8;

    #pragma unroll
    for (int mt = 0; mt < 4; mt++)
        #pragma unroll
        for (int nt = 0; nt < 4; nt++)
            #pragma unroll
            for (int r = 0; r < 4; r++) c[mt][nt][r] = 0.f;

    const int NT = K >> 6;   // BK = 64
    issue_tile(smu, A, B, bm, bn, K, 0,  0); CP_COMMIT;
    issue_tile(smu, A, B, bm, bn, K, 64, 1); CP_COMMIT;

    for (int kt = 0; kt < NT; kt++) {
        CP_WAIT1;
        __syncthreads();
        if (kt + 2 < NT) issue_tile(smu, A, B, bm, bn, K, (kt+2) << 6, (kt+2) % NSTAGE);
        CP_COMMIT;

        const uint32_t sa = smu + (unsigned)(kt % NSTAGE) * STAGE_BYTES;
        const uint32_t sb = sa + AST_BYTES;

        #pragma unroll
        for (int kc = 0; kc < 4; kc++) {
            uint32_t a[4][4];
            #pragma unroll
            for (int mt = 0; mt < 4; mt++)
                ldsm4(a[mt][0], a[mt][1], a[mt][2], a[mt][3],
                      sa + (unsigned)((wm + mt*16 + ar)*KST + kc*16 + ac) * 2);
            uint32_t bf[4][2];
            #pragma unroll
            for (int p = 0; p < 2; p++) {
                uint32_t r0, r1, r2, r3;
                ldsm4(r0, r1, r2, r3,
                      sb + (unsigned)((wn + p*16 + br)*KST + kc*16 + bc) * 2);
                bf[2*p][0]   = r0; bf[2*p][1]   = r1;
                bf[2*p+1][0] = r2; bf[2*p+1][1] = r3;
            }
            #pragma unroll
            for (int mt = 0; mt < 4; mt++)
                #pragma unroll
                for (int nt = 0; nt < 4; nt++)
                    mma_f16(c[mt][nt], a[mt], bf[nt]);
        }
    }
}

// ---------------- GEMM with fp32 output + residual ----------------
__global__ __launch_bounds__(256, 2)
void gemm_res(const __half* __restrict__ A, const __half* __restrict__ B,
              const float* __restrict__ bias, const float* __restrict__ res,
              float* __restrict__ C, int Nn, int K)
{
    extern __shared__ uint32_t smg[];
    uint32_t smu = (uint32_t)__cvta_generic_to_shared(smg);
    const int bm = blockIdx.y * 128;
    const int bn = blockIdx.x * 128;
    float c[4][4][4];
    gemm_main(A, B, bm, bn, K, smu, c);

    const int tid = threadIdx.x, warp = tid >> 5, lane = tid & 31;
    const int g = lane >> 2, t = lane & 3;
    const int wm = (warp >> 2) * 64, wn = (warp & 3) * 32;
    #pragma unroll
    for (int mt = 0; mt < 4; mt++) {
        #pragma unroll
        for (int nt = 0; nt < 4; nt++) {
            int col = bn + wn + nt * 8 + t * 2;
            float2 bi = *(const float2*)(bias + col);
            #pragma unroll
            for (int h = 0; h < 2; h++) {
                int row = bm + wm + mt * 16 + g + h * 8;
                float2 r = *(const float2*)(res + (size_t)row * Nn + col);
                *(float2*)(C + (size_t)row * Nn + col) =
                    make_float2(c[mt][nt][h*2+0] + bi.x + r.x,
                                c[mt][nt][h*2+1] + bi.y + r.y);
            }
        }
    }
}

// ---------------- GEMM with GELU + fp16 output ----------------
__global__ __launch_bounds__(256, 2)
void gemm_gelu(const __half* __restrict__ A, const __half* __restrict__ B,
               const float* __restrict__ bias, __half* __restrict__ C, int Nn, int K)
{
    extern __shared__ uint32_t smg[];
    uint32_t smu = (uint32_t)__cvta_generic_to_shared(smg);
    const int bm = blockIdx.y * 128;
    const int bn = blockIdx.x * 128;
    float c[4][4][4];
    gemm_main(A, B, bm, bn, K, smu, c);

    const int tid = threadIdx.x, warp = tid >> 5, lane = tid & 31;
    const int g = lane >> 2, t = lane & 3;
    const int wm = (warp >> 2) * 64, wn = (warp & 3) * 32;
    #pragma unroll
    for (int mt = 0; mt < 4; mt++) {
        #pragma unroll
        for (int nt = 0; nt < 4; nt++) {
            int col = bn + wn + nt * 8 + t * 2;
            float2 bi = *(const float2*)(bias + col);
            #pragma unroll
            for (int h = 0; h < 2; h++) {
                int row = bm + wm + mt * 16 + g + h * 8;
                *(uint32_t*)(C + (size_t)row * Nn + col) =
                    h2pack(gelu_exact(c[mt][nt][h*2+0] + bi.x),
                           gelu_exact(c[mt][nt][h*2+1] + bi.y));
            }
        }
    }
}

// ---------------- fused QKV projection (fp16 out, scale on Q) ----------------
__global__ __launch_bounds__(256, 2)
void gemm_qkv(const __half* __restrict__ A,
              const __half* __restrict__ Bq, const __half* __restrict__ Bk, const __half* __restrict__ Bv,
              const float* __restrict__ bq, const float* __restrict__ bk, const float* __restrict__ bv,
              __half* __restrict__ Cq, __half* __restrict__ Ck, __half* __restrict__ Cv, int K)
{
    extern __shared__ uint32_t smg[];
    uint32_t smu = (uint32_t)__cvta_generic_to_shared(smg);
    const int bm  = blockIdx.y * 128;
    const int bng = blockIdx.x * 128;
    const int seg = bng >> 10;
    const int bn  = bng & 1023;
    const __half* B   = (seg == 0) ? Bq : (seg == 1) ? Bk : Bv;
    const float* bias = (seg == 0) ? bq : (seg == 1) ? bk : bv;
    __half*      C    = (seg == 0) ? Cq : (seg == 1) ? Ck : Cv;
    const float scale = (seg == 0) ? 0.125f : 1.0f;

    float c[4][4][4];
    gemm_main(A, B, bm, bn, K, smu, c);

    const int tid = threadIdx.x, warp = tid >> 5, lane = tid & 31;
    const int g = lane >> 2, t = lane & 3;
    const int wm = (warp >> 2) * 64, wn = (warp & 3) * 32;
    #pragma unroll
    for (int mt = 0; mt < 4; mt++) {
        #pragma unroll
        for (int nt = 0; nt < 4; nt++) {
            int col = bn + wn + nt * 8 + t * 2;
            float2 bi = *(const float2*)(bias + col);
            #pragma unroll
            for (int h = 0; h < 2; h++) {
                int row = bm + wm + mt * 16 + g + h * 8;
                *(uint32_t*)(C + (size_t)row * 1024 + col) =
                    h2pack((c[mt][nt][h*2+0] + bi.x) * scale,
                           (c[mt][nt][h*2+1] + bi.y) * scale);
            }
        }
    }
}

// ---------------- flash attention, fp16 MMA, ldsm.trans V ----------------
// Br=Bc=64, 128 threads (4 warps); warp tile 16 q-rows x 64 keys.
#define ATST 72   // halves per smem row (144 B)

__global__ __launch_bounds__(128)
void attn_h(const __half* __restrict__ q, const __half* __restrict__ k,
            const __half* __restrict__ v, __half* __restrict__ o)
{
    __shared__ __half Qs[64*ATST];
    __shared__ __half Ks[64*ATST];
    __shared__ __half Vs[64*ATST];   // [key][d] — fragments extracted via ldsm.trans
    const uint32_t qsu = (uint32_t)__cvta_generic_to_shared(Qs);
    const uint32_t ksu = (uint32_t)__cvta_generic_to_shared(Ks);
    const uint32_t vsu = (uint32_t)__cvta_generic_to_shared(Vs);

    const int qb = blockIdx.x;
    const int nh = blockIdx.y;
    const int n  = nh / HH;
    const int hh = nh % HH;
    const int tid  = threadIdx.x;
    const int warp = tid >> 5;
    const int lane = tid & 31;
    const int g = lane >> 2, t = lane & 3;
    const int m0 = warp * 16;
    const int ar = lane & 15, ac = (lane >> 4) * 8;
    const int br = (lane & 7) + ((lane >> 4) << 3), bc = ((lane >> 3) & 1) * 8;
    // trans-ldsm addressing for V: groups (key-lo,d-lo),(key-hi,d-lo),(key-lo,d-hi),(key-hi,d-hi)
    const int vr = (lane & 7) + (((lane >> 3) & 1) << 3);  // key offset within 16
    const int vc = (lane >> 4) * 8;                        // d offset within 16

    // Q tile: [row][d], fp16 (pre-scaled)
    #pragma unroll
    for (int p = 0; p < 4; p++) {
        int idx = tid + p * 128;            // 512 chunks of 8 halves
        int row = idx >> 3, c8 = (idx & 7) * 8;
        *(uint4*)&Qs[row*ATST + c8] =
            *(const uint4*)(q + ((size_t)((qb*64+row)*NB + n)*EE + hh*DD + c8));
    }

    float m_i[2] = {-1e30f, -1e30f};
    float l_i[2] = {0.f, 0.f};
    float accO[8][4];
    #pragma unroll
    for (int dt = 0; dt < 8; dt++)
        #pragma unroll
        for (int r = 0; r < 4; r++) accO[dt][r] = 0.f;

    for (int jb = 0; jb <= qb; jb++) {
        __syncthreads();
        // K and V tiles, both [row][d] vectorized
        #pragma unroll
        for (int p = 0; p < 4; p++) {
            int idx = tid + p * 128;
            int row = idx >> 3, c8 = (idx & 7) * 8;
            size_t goff = (size_t)((jb*64+row)*NB + n)*EE + hh*DD + c8;
            *(uint4*)&Ks[row*ATST + c8] = *(const uint4*)(k + goff);
            *(uint4*)&Vs[row*ATST + c8] = *(const uint4*)(v + goff);
        }
        __syncthreads();

        // S = Q K^T (16 x 64 per warp)
        float sc[8][4];
        #pragma unroll
        for (int nt = 0; nt < 8; nt++)
            #pragma unroll
            for (int r = 0; r < 4; r++) sc[nt][r] = 0.f;

        #pragma unroll
        for (int kc = 0; kc < 4; kc++) {
            uint32_t a[4];
            ldsm4(a[0], a[1], a[2], a[3],
                  qsu + (unsigned)((m0 + ar)*ATST + kc*16 + ac) * 2);
            #pragma unroll
            for (int p = 0; p < 4; p++) {
                uint32_t r0, r1, r2, r3;
                ldsm4(r0, r1, r2, r3,
                      ksu + (unsigned)((p*16 + br)*ATST + kc*16 + bc) * 2);
                uint32_t b0[2] = {r0, r1}, b1[2] = {r2, r3};
                mma_f16(sc[2*p],   a, b0);
                mma_f16(sc[2*p+1], a, b1);
            }
        }

        // causal mask on diagonal tile
        if (jb == qb) {
            int r0 = m0 + g, r1 = m0 + g + 8;
            #pragma unroll
            for (int nt = 0; nt < 8; nt++) {
                int col = nt * 8 + t * 2;
                if (col     > r0) sc[nt][0] = -1e30f;
                if (col + 1 > r0) sc[nt][1] = -1e30f;
                if (col     > r1) sc[nt][2] = -1e30f;
                if (col + 1 > r1) sc[nt][3] = -1e30f;
            }
        }

        // online softmax (rows g, g+8; quad reduction)
        float mx0 = -1e30f, mx1 = -1e30f;
        #pragma unroll
        for (int nt = 0; nt < 8; nt++) {
            mx0 = fmaxf(mx0, fmaxf(sc[nt][0], sc[nt][1]));
            mx1 = fmaxf(mx1, fmaxf(sc[nt][2], sc[nt][3]));
        }
        #pragma unroll
        for (int off = 1; off < 4; off <<= 1) {
            mx0 = fmaxf(mx0, __shfl_xor_sync(0xffffffffu, mx0, off));
            mx1 = fmaxf(mx1, __shfl_xor_sync(0xffffffffu, mx1, off));
        }
        float mn0 = fmaxf(m_i[0], mx0), mn1 = fmaxf(m_i[1], mx1);
        float corr0 = __expf(m_i[0] - mn0), corr1 = __expf(m_i[1] - mn1);
        float sum0 = 0.f, sum1 = 0.f;
        #pragma unroll
        for (int nt = 0; nt < 8; nt++) {
            sc[nt][0] = __expf(sc[nt][0] - mn0); sum0 += sc[nt][0];
            sc[nt][1] = __expf(sc[nt][1] - mn0); sum0 += sc[nt][1];
            sc[nt][2] = __expf(sc[nt][2] - mn1); sum1 += sc[nt][2];
            sc[nt][3] = __expf(sc[nt][3] - mn1); sum1 += sc[nt][3];
        }
        #pragma unroll
        for (int off = 1; off < 4; off <<= 1) {
            sum0 += __shfl_xor_sync(0xffffffffu, sum0, off);
            sum1 += __shfl_xor_sync(0xffffffffu, sum1, off);
        }
        l_i[0] = l_i[0] * corr0 + sum0;
        l_i[1] = l_i[1] * corr1 + sum1;
        m_i[0] = mn0; m_i[1] = mn1;
        #pragma unroll
        for (int dt = 0; dt < 8; dt++) {
            accO[dt][0] *= corr0; accO[dt][1] *= corr0;
            accO[dt][2] *= corr1; accO[dt][3] *= corr1;
        }

        // O += P V: S C-frag IS the P A-frag; V B-frags via ldsm.trans from [key][d]
        #pragma unroll
        for (int kc = 0; kc < 4; kc++) {
            uint32_t a[4];
            a[0] = h2pack(sc[2*kc][0],   sc[2*kc][1]);     // m=g,   k low
            a[1] = h2pack(sc[2*kc][2],   sc[2*kc][3]);     // m=g+8, k low
            a[2] = h2pack(sc[2*kc+1][0], sc[2*kc+1][1]);   // m=g,   k high
            a[3] = h2pack(sc[2*kc+1][2], sc[2*kc+1][3]);   // m=g+8, k high
            #pragma unroll
            for (int dp = 0; dp < 4; dp++) {
                uint32_t r0, r1, r2, r3;
                ldsm4t(r0, r1, r2, r3,
                       vsu + (unsigned)((kc*16 + vr)*ATST + dp*16 + vc) * 2);
                uint32_t b0[2] = {r0, r1}, b1[2] = {r2, r3};
                mma_f16(accO[2*dp],   a, b0);
                mma_f16(accO[2*dp+1], a, b1);
            }
        }
    }

    // normalize + store fp16
    float inv0 = 1.0f / l_i[0], inv1 = 1.0f / l_i[1];
    int l0 = qb*64 + m0 + g;
    int l1 = l0 + 8;
    #pragma unroll
    for (int dt = 0; dt < 8; dt++) {
        int d = hh*DD + dt*8 + t*2;
        *(uint32_t*)(o + ((size_t)(l0*NB + n)*EE + d)) =
            h2pack(accO[dt][0]*inv0, accO[dt][1]*inv0);
        *(uint32_t*)(o + ((size_t)(l1*NB + n)*EE + d)) =
            h2pack(accO[dt][2]*inv1, accO[dt][3]*inv1);
    }
}

// ---------------- launch ----------------
extern "C" void kernel_launch(void* const* d_in, const int* in_sizes, int n_in,
                              void* d_out, int out_size)
{
    const float* x     = (const float*)d_in[0];
    const float* ln1_w = (const float*)d_in[1];
    const float* ln1_b = (const float*)d_in[2];
    const float* wq    = (const float*)d_in[3];
    const float* bq    = (const float*)d_in[4];
    const float* wk    = (const float*)d_in[5];
    const float* bk    = (const float*)d_in[6];
    const float* wv    = (const float*)d_in[7];
    const float* bv    = (const float*)d_in[8];
    const float* wout  = (const float*)d_in[9];
    const float* bout  = (const float*)d_in[10];
    const float* ln2_w = (const float*)d_in[11];
    const float* ln2_b = (const float*)d_in[12];
    const float* fc1_w = (const float*)d_in[13];
    const float* fc1_b = (const float*)d_in[14];
    const float* fc2_w = (const float*)d_in[15];
    const float* fc2_b = (const float*)d_in[16];
    float* out = (float*)d_out;

    __half *h, *q, *k, *v, *o, *h2, *mid;
    __half *cwq, *cwk, *cwv, *cwo, *cw1, *cw2;
    float  *x2;
    cudaGetSymbolAddress((void**)&h,   g_h);
    cudaGetSymbolAddress((void**)&q,   g_q);
    cudaGetSymbolAddress((void**)&k,   g_k);
    cudaGetSymbolAddress((void**)&v,   g_v);
    cudaGetSymbolAddress((void**)&o,   g_o);
    cudaGetSymbolAddress((void**)&h2,  g_h2);
    cudaGetSymbolAddress((void**)&mid, g_mid);
    cudaGetSymbolAddress((void**)&x2,  g_x2);
    cudaGetSymbolAddress((void**)&cwq, g_wq);
    cudaGetSymbolAddress((void**)&cwk, g_wk);
    cudaGetSymbolAddress((void**)&cwv, g_wv);
    cudaGetSymbolAddress((void**)&cwo, g_wo);
    cudaGetSymbolAddress((void**)&cw1, g_w1);
    cudaGetSymbolAddress((void**)&cw2, g_w2);

    cudaFuncSetAttribute(gemm_qkv,  cudaFuncAttributeMaxDynamicSharedMemorySize, GEMM_SMEM);
    cudaFuncSetAttribute(gemm_res,  cudaFuncAttributeMaxDynamicSharedMemorySize, GEMM_SMEM);
    cudaFuncSetAttribute(gemm_gelu, cudaFuncAttributeMaxDynamicSharedMemorySize, GEMM_SMEM);

    // fused weight conversion (fp32 -> fp16), one launch: 3145728 float4 chunks
    f2h_all<<<12288, 256>>>((const float4*)wq, (const float4*)wk, (const float4*)wv,
                            (const float4*)wout, (const float4*)fc1_w, (const float4*)fc2_w,
                            (uint32_t*)cwq, (uint32_t*)cwk, (uint32_t*)cwv,
                            (uint32_t*)cwo, (uint32_t*)cw1, (uint32_t*)cw2);

    // LN1: x -> h (fp16)
    ln_kernel<<<ROWS, 256>>>(x, ln1_w, ln1_b, h);

    // fused QKV (M=4096, N=3*1024, K=1024); scale folded into Q
    dim3 gqkv(3 * EE / 128, ROWS / 128);
    gemm_qkv<<<gqkv, 256, GEMM_SMEM>>>(h, cwq, cwk, cwv, bq, bk, bv, q, k, v, EE);

    // causal flash attention (fp16 MMA)
    dim3 ga(LL / 64, NB * HH);
    attn_h<<<ga, 128>>>(q, k, v, o);

    // out projection + residual(x) -> x2 (fp32)
    dim3 g1024(EE / 128, ROWS / 128);
    gemm_res<<<g1024, 256, GEMM_SMEM>>>(o, cwo, bout, x, x2, EE, EE);

    // LN2: x2 -> h2 (fp16)
    ln_kernel<<<ROWS, 256>>>(x2, ln2_w, ln2_b, h2);

    // FC1 + GELU -> mid (fp16)
    dim3 g4096(FF / 128, ROWS / 128);
    gemm_gelu<<<g4096, 256, GEMM_SMEM>>>(h2, cw1, fc1_b, mid, FF, EE);

    // FC2 + residual(x2) -> out (fp32)
    gemm_res<<<g1024, 256, GEMM_SMEM>>>(mid, cw2, fc2_b, x2, out, EE, FF);
}